// round 4
// baseline (speedup 1.0000x reference)
#include <cuda_runtime.h>
#include <cstdint>

#define WS    8
#define MQ    4
#define HEADS 8
#define DIM   256
#define HD    32
#define BATCH 4
#define IMGH  128
#define IMGW  128
#define NWIN  256
#define BW    (BATCH*NWIN)   // 1024 windows
#define WS2   64
#define NQ    (MQ*WS2)       // 256
#define ROWS_Q  (BW*NQ)      // 262144
#define ROWS_KV (BW*WS2)     // 65536

__device__ float g_q  [ROWS_Q  * DIM];
__device__ float g_kv [ROWS_KV * 2 * DIM];
__device__ float g_att[ROWS_Q  * DIM];

__device__ __forceinline__ uint32_t f2tf(float x) {
    uint32_t u;
    asm("cvt.rna.tf32.f32 %0, %1;" : "=r"(u) : "f"(x));
    return u;
}

__device__ __forceinline__ void mma_tf32(float c[4],
    uint32_t a0, uint32_t a1, uint32_t a2, uint32_t a3,
    uint32_t b0, uint32_t b1)
{
    asm volatile(
        "mma.sync.aligned.m16n8k8.row.col.f32.tf32.tf32.f32 "
        "{%0,%1,%2,%3}, {%4,%5,%6,%7}, {%8,%9}, {%0,%1,%2,%3};"
        : "+f"(c[0]), "+f"(c[1]), "+f"(c[2]), "+f"(c[3])
        : "r"(a0), "r"(a1), "r"(a2), "r"(a3), "r"(b0), "r"(b1));
}

// packed fp32x2 helpers (sm_103a FFMA2 path)
__device__ __forceinline__ void ffma2(unsigned long long& acc,
                                      unsigned long long a, unsigned long long b) {
    asm("fma.rn.f32x2 %0, %1, %2, %0;" : "+l"(acc) : "l"(a), "l"(b));
}
__device__ __forceinline__ unsigned long long packf2(float lo, float hi) {
    unsigned long long r;
    asm("mov.b64 %0, {%1, %2};" : "=l"(r) : "f"(lo), "f"(hi));
    return r;
}
__device__ __forceinline__ void unpackf2(unsigned long long v, float& lo, float& hi) {
    asm("mov.b64 {%0, %1}, %2;" : "=f"(lo), "=f"(hi) : "l"(v));
}

// ---------------------------------------------------------------------------
// tf32 GEMM: C[M,N] = A[M,256] @ W[256,N] + bias[N]
// Block 128x128, BK=16, 8 warps, warp tile 32x64 (4x2 warp grid).
// Smem stores (k, k+4) tf32 pairs; row stride 12 uint2 -> conflict-free frags.
// ---------------------------------------------------------------------------
template<bool GATHER>
__global__ __launch_bounds__(256) void gemm_tf32_kernel(
    const float* __restrict__ A, const float* __restrict__ W,
    const float* __restrict__ bias, float* __restrict__ C, int N)
{
    __shared__ uint2 As2[128][12];   // [row][c] pair {A[row][k8(c)], A[row][k8(c)+4]}
    __shared__ uint2 Wt2[128][12];   // [n][c]   pair {W[k8(c)][n],   W[k8(c)+4][n]}
    const int t    = threadIdx.x;
    const int bm   = blockIdx.y, bn = blockIdx.x;
    const int lane = t & 31, warp = t >> 5;
    const int wm   = warp >> 1;      // 0..3 (32-row strip)
    const int wn   = warp & 1;       // 0..1 (64-col strip)
    const int g    = lane >> 2;
    const int tq   = lane & 3;

    // A stager: t<128, one full row of 16 k-values
    const float* Arow = nullptr;
    if (t < 128) {
        if (GATHER) {
            const int r    = bm * 128 + t;
            const int wwin = r >> 6, p = r & 63;
            const int b    = wwin >> 8, widx = wwin & 255;
            const int wy   = widx >> 4, wx = widx & 15;
            const int py   = wy * 8 + (p >> 3);
            const int px   = wx * 8 + (p & 7);
            Arow = A + (((size_t)b * IMGH + py) * IMGW + px) * DIM;
        } else {
            Arow = A + (size_t)(bm * 128 + t) * DIM;
        }
    }
    const int wn_col = (t >= 128) ? (t - 128) : 0;            // W stager column 0..127
    const float* Wcol = W + bn * 128 + wn_col;

    float acc[2][8][4];
    #pragma unroll
    for (int mi = 0; mi < 2; mi++)
        #pragma unroll
        for (int ni = 0; ni < 8; ni++)
            #pragma unroll
            for (int j = 0; j < 4; j++) acc[mi][ni][j] = 0.f;

    for (int k0 = 0; k0 < DIM; k0 += 16) {
        // ---- stage ----
        if (t < 128) {
            float f[16];
            float4 v0 = *(const float4*)(Arow + k0);
            float4 v1 = *(const float4*)(Arow + k0 + 4);
            float4 v2 = *(const float4*)(Arow + k0 + 8);
            float4 v3 = *(const float4*)(Arow + k0 + 12);
            f[0]=v0.x; f[1]=v0.y; f[2]=v0.z; f[3]=v0.w;
            f[4]=v1.x; f[5]=v1.y; f[6]=v1.z; f[7]=v1.w;
            f[8]=v2.x; f[9]=v2.y; f[10]=v2.z; f[11]=v2.w;
            f[12]=v3.x; f[13]=v3.y; f[14]=v3.z; f[15]=v3.w;
            #pragma unroll
            for (int j = 0; j < 8; j++) {
                int c = (j + (t & 7)) & 7;           // rotate to cap store conflicts
                int k = ((c >> 2) << 3) + (c & 3);   // k8(c)
                As2[t][c] = make_uint2(f2tf(f[k]), f2tf(f[k + 4]));
            }
        } else {
            float wv[16];
            #pragma unroll
            for (int k = 0; k < 16; k++)
                wv[k] = Wcol[(size_t)(k0 + k) * N];  // lanes n-consecutive: coalesced
            #pragma unroll
            for (int j = 0; j < 8; j++) {
                int c = (j + (wn_col & 7)) & 7;
                int k = ((c >> 2) << 3) + (c & 3);
                Wt2[wn_col][c] = make_uint2(f2tf(wv[k]), f2tf(wv[k + 4]));
            }
        }
        __syncthreads();

        // ---- compute 2 k-steps of 8 ----
        #pragma unroll
        for (int ks = 0; ks < 2; ks++) {
            const int coff = ks * 4 + tq;
            uint2 al[2], ah[2];
            #pragma unroll
            for (int mi = 0; mi < 2; mi++) {
                const int r0 = wm * 32 + mi * 16 + g;
                al[mi] = As2[r0][coff];
                ah[mi] = As2[r0 + 8][coff];
            }
            uint2 bfv[8];
            #pragma unroll
            for (int ni = 0; ni < 8; ni++)
                bfv[ni] = Wt2[wn * 64 + ni * 8 + g][coff];
            #pragma unroll
            for (int mi = 0; mi < 2; mi++)
                #pragma unroll
                for (int ni = 0; ni < 8; ni++)
                    mma_tf32(acc[mi][ni], al[mi].x, ah[mi].x, al[mi].y, ah[mi].y,
                             bfv[ni].x, bfv[ni].y);
        }
        __syncthreads();
    }

    // ---- epilogue ----
    #pragma unroll
    for (int mi = 0; mi < 2; mi++) {
        const int r0 = bm * 128 + wm * 32 + mi * 16 + g;
        #pragma unroll
        for (int ni = 0; ni < 8; ni++) {
            const int col = bn * 128 + wn * 64 + ni * 8 + 2 * tq;
            float2 bv = *(const float2*)(bias + col);
            float2 o0 = make_float2(acc[mi][ni][0] + bv.x, acc[mi][ni][1] + bv.y);
            float2 o1 = make_float2(acc[mi][ni][2] + bv.x, acc[mi][ni][3] + bv.y);
            *(float2*)(C + (size_t)r0 * N + col)       = o0;
            *(float2*)(C + (size_t)(r0 + 8) * N + col) = o1;
        }
    }
}

// ---------------------------------------------------------------------------
// Attention: one block per (window, head), 256 threads = 256 queries.
// Inner loops on packed fma.rn.f32x2 (FFMA2): K/V smem read as double2 so
// operands occupy b64 register pairs with no packing MOVs.
// ---------------------------------------------------------------------------
__global__ __launch_bounds__(256) void attn_kernel(const float* __restrict__ btab)
{
    __shared__ float4 Ks[WS2 * 8];
    __shared__ float4 Vs[WS2 * 8];
    __shared__ float  Bs[WS2][WS2 + 1];

    const int blk = blockIdx.x;
    const int win = blk >> 3;
    const int h   = blk & 7;
    const int t   = threadIdx.x;

    {
        const size_t base = (size_t)win * WS2 * (2 * DIM) + h * HD;
        #pragma unroll
        for (int i = 0; i < 2; i++) {
            int idx = t + i * 256;
            int kr = idx >> 3, dg = idx & 7;
            Ks[idx] = *(const float4*)(g_kv + base + (size_t)kr * 512 + dg * 4);
            Vs[idx] = *(const float4*)(g_kv + base + DIM + (size_t)kr * 512 + dg * 4);
        }
    }
    #pragma unroll
    for (int i = 0; i < 16; i++) {
        int e  = t + i * 256;
        int qp = e >> 6, kp = e & 63;
        int dr = (qp >> 3) - (kp >> 3) + 7;
        int dc = (qp & 7)  - (kp & 7)  + 7;
        Bs[qp][kp] = btab[(dr * 15 + dc) * HEADS + h];
    }
    __syncthreads();

    const double2* Ks2 = (const double2*)Ks;
    const double2* Vs2 = (const double2*)Vs;

    const float scale = 0.17677669529663687f;  // 32^-0.5
    unsigned long long q2[16];
    {
        const float* qp = g_q + ((size_t)(win * NQ + t)) * DIM + h * HD;
        #pragma unroll
        for (int j = 0; j < 8; j++) {
            float4 v = *(const float4*)(qp + j * 4);
            q2[2 * j]     = packf2(v.x * scale, v.y * scale);
            q2[2 * j + 1] = packf2(v.z * scale, v.w * scale);
        }
    }

    const int qb = t & 63;
    float s[64];
    float mx = -1e30f;
    #pragma unroll
    for (int k = 0; k < 64; k++) {
        unsigned long long acc2 = 0ull;  // {0.f, 0.f}
        #pragma unroll
        for (int j = 0; j < 8; j++) {
            double2 kd = Ks2[k * 8 + j];
            ffma2(acc2, q2[2 * j],     __double_as_longlong(kd.x));
            ffma2(acc2, q2[2 * j + 1], __double_as_longlong(kd.y));
        }
        float lo, hi;
        unpackf2(acc2, lo, hi);
        float v = lo + hi + Bs[qb][k];
        s[k] = v;
        mx = fmaxf(mx, v);
    }
    float sum = 0.f;
    #pragma unroll
    for (int k = 0; k < 64; k++) { float e = __expf(s[k] - mx); s[k] = e; sum += e; }
    const float inv = 1.f / sum;

    unsigned long long o2[16];
    #pragma unroll
    for (int j = 0; j < 16; j++) o2[j] = 0ull;
    #pragma unroll
    for (int k = 0; k < 64; k++) {
        unsigned long long p2 = packf2(s[k], s[k]);
        #pragma unroll
        for (int j = 0; j < 8; j++) {
            double2 vd = Vs2[k * 8 + j];
            ffma2(o2[2 * j],     p2, __double_as_longlong(vd.x));
            ffma2(o2[2 * j + 1], p2, __double_as_longlong(vd.y));
        }
    }

    float* op = g_att + ((size_t)(win * NQ + t)) * DIM + h * HD;
    #pragma unroll
    for (int j = 0; j < 8; j++) {
        float x0, x1, x2, x3;
        unpackf2(o2[2 * j], x0, x1);
        unpackf2(o2[2 * j + 1], x2, x3);
        float4 v = make_float4(x0 * inv, x1 * inv, x2 * inv, x3 * inv);
        *(float4*)(op + j * 4) = v;
    }
}

// ---------------------------------------------------------------------------
extern "C" void kernel_launch(void* const* d_in, const int* in_sizes, int n_in,
                              void* d_out, int out_size)
{
    const float* gauss = (const float*)d_in[0];
    const float* img   = (const float*)d_in[1];
    const float* btab  = (const float*)d_in[2];
    const float* Wq    = (const float*)d_in[3];
    const float* bq    = (const float*)d_in[4];
    const float* Wkv   = (const float*)d_in[5];
    const float* bkv   = (const float*)d_in[6];
    const float* Wp    = (const float*)d_in[7];
    const float* bp    = (const float*)d_in[8];
    float* out = (float*)d_out;

    void* pq = nullptr;   cudaGetSymbolAddress(&pq, g_q);
    void* pkv = nullptr;  cudaGetSymbolAddress(&pkv, g_kv);
    void* pa = nullptr;   cudaGetSymbolAddress(&pa, g_att);

    // 1) Q projection: [262144,256] @ [256,256] + bq
    gemm_tf32_kernel<false><<<dim3(DIM / 128, ROWS_Q / 128), 256>>>(gauss, Wq, bq, (float*)pq, DIM);
    // 2) KV projection with window gather: [65536,256] @ [256,512] + bkv
    gemm_tf32_kernel<true><<<dim3((2 * DIM) / 128, ROWS_KV / 128), 256>>>(img, Wkv, bkv, (float*)pkv, 2 * DIM);
    // 3) Attention per (window, head)
    attn_kernel<<<BW * HEADS, 256>>>(btab);
    // 4) Output projection -> d_out
    gemm_tf32_kernel<false><<<dim3(DIM / 128, ROWS_Q / 128), 256>>>((const float*)pa, Wp, bp, out, DIM);
}

// round 6
// speedup vs baseline: 1.0583x; 1.0583x over previous
#include <cuda_runtime.h>
#include <cstdint>

#define WS    8
#define MQ    4
#define HEADS 8
#define DIM   256
#define HD    32
#define BATCH 4
#define IMGH  128
#define IMGW  128
#define NWIN  256
#define BW    (BATCH*NWIN)   // 1024 windows
#define WS2   64
#define NQ    (MQ*WS2)       // 256
#define ROWS_Q  (BW*NQ)      // 262144
#define ROWS_KV (BW*WS2)     // 65536

__device__ float g_q  [ROWS_Q  * DIM];
__device__ float g_kv [ROWS_KV * 2 * DIM];
__device__ float g_att[ROWS_Q  * DIM];

__device__ __forceinline__ uint32_t f2tf(float x) {
    uint32_t u;
    asm("cvt.rna.tf32.f32 %0, %1;" : "=r"(u) : "f"(x));
    return u;
}

__device__ __forceinline__ void mma_tf32(float c[4],
    uint32_t a0, uint32_t a1, uint32_t a2, uint32_t a3,
    uint32_t b0, uint32_t b1)
{
    asm volatile(
        "mma.sync.aligned.m16n8k8.row.col.f32.tf32.tf32.f32 "
        "{%0,%1,%2,%3}, {%4,%5,%6,%7}, {%8,%9}, {%0,%1,%2,%3};"
        : "+f"(c[0]), "+f"(c[1]), "+f"(c[2]), "+f"(c[3])
        : "r"(a0), "r"(a1), "r"(a2), "r"(a3), "r"(b0), "r"(b1));
}

// ---------------------------------------------------------------------------
// tf32 GEMM: C[M,N] = A[M,256] @ W[256,N] + bias[N]
// Block 128x64, BK=16, 8 warps (4x2), warp tile 32x32.
// Smem holds {k, k+4} tf32 pairs -> one LDS.64 per fragment pair.
// ---------------------------------------------------------------------------
template<bool GATHER>
__global__ __launch_bounds__(256) void gemm_tf32_kernel(
    const float* __restrict__ A, const float* __restrict__ W,
    const float* __restrict__ bias, float* __restrict__ C, int N)
{
    __shared__ uint2 As2[128][9];   // [row][c] c = ks*4+tq : {A[k],A[k+4]}
    __shared__ uint2 Wt2[64][9];    // [n][c]            : {W[k][n],W[k+4][n]}
    const int t    = threadIdx.x;
    const int bm   = blockIdx.y, bn = blockIdx.x;
    const int lane = t & 31, warp = t >> 5;
    const int wm   = warp >> 1;      // 0..3
    const int wnn  = warp & 1;       // 0..1
    const int g    = lane >> 2;
    const int tq   = lane & 3;

    // A staging: thread -> (row t>>1, k8-group t&1)
    const int arow = t >> 1, as = (t & 1);
    const float* Arow;
    if (GATHER) {
        const int r    = bm * 128 + arow;
        const int wwin = r >> 6, p = r & 63;
        const int b    = wwin >> 8, widx = wwin & 255;
        const int wy   = widx >> 4, wx = widx & 15;
        const int py   = wy * 8 + (p >> 3);
        const int px   = wx * 8 + (p & 7);
        Arow = A + (((size_t)b * IMGH + py) * IMGW + px) * DIM;
    } else {
        Arow = A + (size_t)(bm * 128 + arow) * DIM;
    }
    // W staging: thread -> (k = t>>4, 4 n at (t&15)*4)
    const int wk = t >> 4, wn4 = (t & 15) * 4;
    const float* Wp = W + (size_t)wk * N + bn * 64 + wn4;
    const int ws_   = wk >> 3;
    const int wwith = wk & 7;
    const int whalf = wwith >> 2;
    const int wtq   = wwith & 3;
    uint32_t* Wt_w  = (uint32_t*)Wt2;     // word view, row stride 18

    float acc[2][4][4];
    #pragma unroll
    for (int mi = 0; mi < 2; mi++)
        #pragma unroll
        for (int ni = 0; ni < 4; ni++)
            #pragma unroll
            for (int j = 0; j < 4; j++) acc[mi][ni][j] = 0.f;

    for (int k0 = 0; k0 < DIM; k0 += 16) {
        {
            float4 v0 = *(const float4*)(Arow + k0 + as * 8);
            float4 v1 = *(const float4*)(Arow + k0 + as * 8 + 4);
            As2[arow][as * 4 + 0] = make_uint2(f2tf(v0.x), f2tf(v1.x));
            As2[arow][as * 4 + 1] = make_uint2(f2tf(v0.y), f2tf(v1.y));
            As2[arow][as * 4 + 2] = make_uint2(f2tf(v0.z), f2tf(v1.z));
            As2[arow][as * 4 + 3] = make_uint2(f2tf(v0.w), f2tf(v1.w));
        }
        {
            float4 wv = *(const float4*)(Wp + (size_t)k0 * N);
            const int cw = (ws_ * 4 + wtq) * 2 + whalf;
            Wt_w[(wn4 + 0) * 18 + cw] = f2tf(wv.x);
            Wt_w[(wn4 + 1) * 18 + cw] = f2tf(wv.y);
            Wt_w[(wn4 + 2) * 18 + cw] = f2tf(wv.z);
            Wt_w[(wn4 + 3) * 18 + cw] = f2tf(wv.w);
        }
        __syncthreads();

        #pragma unroll
        for (int ks = 0; ks < 2; ks++) {
            const int c = ks * 4 + tq;
            uint2 al[2], ah[2];
            #pragma unroll
            for (int mi = 0; mi < 2; mi++) {
                const int r0 = wm * 32 + mi * 16 + g;
                al[mi] = As2[r0][c];
                ah[mi] = As2[r0 + 8][c];
            }
            uint2 bf[4];
            #pragma unroll
            for (int ni = 0; ni < 4; ni++)
                bf[ni] = Wt2[wnn * 32 + ni * 8 + g][c];
            #pragma unroll
            for (int mi = 0; mi < 2; mi++)
                #pragma unroll
                for (int ni = 0; ni < 4; ni++)
                    mma_tf32(acc[mi][ni], al[mi].x, ah[mi].x, al[mi].y, ah[mi].y,
                             bf[ni].x, bf[ni].y);
        }
        __syncthreads();
    }

    #pragma unroll
    for (int mi = 0; mi < 2; mi++) {
        const int r0 = bm * 128 + wm * 32 + mi * 16 + g;
        #pragma unroll
        for (int ni = 0; ni < 4; ni++) {
            const int col = bn * 64 + wnn * 32 + ni * 8 + 2 * tq;
            float2 bv = *(const float2*)(bias + col);
            float2 o0 = make_float2(acc[mi][ni][0] + bv.x, acc[mi][ni][1] + bv.y);
            float2 o1 = make_float2(acc[mi][ni][2] + bv.x, acc[mi][ni][3] + bv.y);
            *(float2*)(C + (size_t)r0 * N + col)       = o0;
            *(float2*)(C + (size_t)(r0 + 8) * N + col) = o1;
        }
    }
}

// ---------------------------------------------------------------------------
// Tensor-core attention. Block = (window, head), 8 warps x 32 query rows.
// Dynamic smem layout (bytes):
//   [0, 69632)        Ps (uint32 [256][68]) — unions over Qs2 (uint2 [256][17])
//   [69632, 78336)    Kt2 (uint2 [64][17])
//   [78336, 86784)    Vt2 (uint2 [32][33])
//   [86784, 103424)   Bs  (float [64][65])
// ---------------------------------------------------------------------------
#define ATTN_SMEM_BYTES 103424

__global__ __launch_bounds__(256) void attn_mma_kernel(const float* __restrict__ btab)
{
    extern __shared__ char smem[];
    uint32_t* Ps_w = (uint32_t*)smem;                       // [256][68]
    uint2*    Qs2  = (uint2*)smem;                          // [256][17]
    uint2*    Kt2  = (uint2*)(smem + 69632);                // [64][17]
    uint2*    Vt2  = (uint2*)(smem + 78336);                // [32][33]
    uint32_t* Vt_w = (uint32_t*)(smem + 78336);             // word view, stride 66
    float*    Bsf  = (float*)(smem + 86784);                // [64][65]

    const int blk = blockIdx.x;
    const int win = blk >> 3;
    const int h   = blk & 7;
    const int t   = threadIdx.x;
    const int lane = t & 31, warp = t >> 5;
    const int g   = lane >> 2;
    const int tq  = lane & 3;

    const float scale = 0.17677669529663687f;  // 32^-0.5

    // ---- stage Q (scaled, tf32 pairs) : thread t -> query row t ----
    {
        const float* qp = g_q + ((size_t)(win * NQ + t)) * DIM + h * HD;
        #pragma unroll
        for (int s = 0; s < 4; s++) {
            float4 v0 = *(const float4*)(qp + s * 8);
            float4 v1 = *(const float4*)(qp + s * 8 + 4);
            Qs2[t * 17 + s * 4 + 0] = make_uint2(f2tf(v0.x * scale), f2tf(v1.x * scale));
            Qs2[t * 17 + s * 4 + 1] = make_uint2(f2tf(v0.y * scale), f2tf(v1.y * scale));
            Qs2[t * 17 + s * 4 + 2] = make_uint2(f2tf(v0.z * scale), f2tf(v1.z * scale));
            Qs2[t * 17 + s * 4 + 3] = make_uint2(f2tf(v0.w * scale), f2tf(v1.w * scale));
        }
    }
    // ---- stage K (threads 0..63) and V-transposed (threads 64..127) ----
    if (t < 64) {
        const float* kp = g_kv + (size_t)(win * WS2 + t) * 512 + h * HD;
        #pragma unroll
        for (int s = 0; s < 4; s++) {
            float4 v0 = *(const float4*)(kp + s * 8);
            float4 v1 = *(const float4*)(kp + s * 8 + 4);
            Kt2[t * 17 + s * 4 + 0] = make_uint2(f2tf(v0.x), f2tf(v1.x));
            Kt2[t * 17 + s * 4 + 1] = make_uint2(f2tf(v0.y), f2tf(v1.y));
            Kt2[t * 17 + s * 4 + 2] = make_uint2(f2tf(v0.z), f2tf(v1.z));
            Kt2[t * 17 + s * 4 + 3] = make_uint2(f2tf(v0.w), f2tf(v1.w));
        }
    } else if (t < 128) {
        const int key = t - 64;
        const float* vp = g_kv + (size_t)(win * WS2 + key) * 512 + DIM + h * HD;
        const int s = key >> 3, within = key & 7;
        const int half = within >> 2, tqv = within & 3;
        const int cw = (s * 4 + tqv) * 2 + half;
        #pragma unroll
        for (int d = 0; d < 32; d += 4) {
            float4 v = *(const float4*)(vp + d);
            Vt_w[(d + 0) * 66 + cw] = f2tf(v.x);
            Vt_w[(d + 1) * 66 + cw] = f2tf(v.y);
            Vt_w[(d + 2) * 66 + cw] = f2tf(v.z);
            Vt_w[(d + 3) * 66 + cw] = f2tf(v.w);
        }
    }
    // ---- stage bias ----
    #pragma unroll
    for (int i = 0; i < 16; i++) {
        int e  = t + i * 256;
        int qp = e >> 6, kp = e & 63;
        int dr = (qp >> 3) - (kp >> 3) + 7;
        int dc = (qp & 7)  - (kp & 7)  + 7;
        Bsf[qp * 65 + kp] = btab[(dr * 15 + dc) * HEADS + h];
    }
    __syncthreads();

    // ---- QK^T : warp tile 32(q) x 64(k), K=32 ----
    float acc[2][8][4];
    #pragma unroll
    for (int mi = 0; mi < 2; mi++)
        #pragma unroll
        for (int ni = 0; ni < 8; ni++)
            #pragma unroll
            for (int j = 0; j < 4; j++) acc[mi][ni][j] = 0.f;

    #pragma unroll
    for (int ks = 0; ks < 4; ks++) {
        const int c = ks * 4 + tq;
        uint2 al[2], ah[2];
        #pragma unroll
        for (int mi = 0; mi < 2; mi++) {
            const int r0 = warp * 32 + mi * 16 + g;
            al[mi] = Qs2[r0 * 17 + c];
            ah[mi] = Qs2[(r0 + 8) * 17 + c];
        }
        uint2 bf[8];
        #pragma unroll
        for (int ni = 0; ni < 8; ni++)
            bf[ni] = Kt2[(ni * 8 + g) * 17 + c];
        #pragma unroll
        for (int mi = 0; mi < 2; mi++)
            #pragma unroll
            for (int ni = 0; ni < 8; ni++)
                mma_tf32(acc[mi][ni], al[mi].x, ah[mi].x, al[mi].y, ah[mi].y,
                         bf[ni].x, bf[ni].y);
    }
    __syncthreads();   // all warps done reading Qs2 before P overwrites it

    // ---- bias + softmax (scalar bias loads: 65-stride rows are 4B-aligned only)
    float inv_[2][2];
    #pragma unroll
    for (int mi = 0; mi < 2; mi++) {
        const int rA = warp * 32 + mi * 16 + g;
        const int qA = rA & 63, qB = (rA + 8) & 63;
        float mA = -1e30f, mB = -1e30f;
        #pragma unroll
        for (int ni = 0; ni < 8; ni++) {
            const int col = ni * 8 + 2 * tq;
            acc[mi][ni][0] += Bsf[qA * 65 + col];
            acc[mi][ni][1] += Bsf[qA * 65 + col + 1];
            acc[mi][ni][2] += Bsf[qB * 65 + col];
            acc[mi][ni][3] += Bsf[qB * 65 + col + 1];
            mA = fmaxf(mA, fmaxf(acc[mi][ni][0], acc[mi][ni][1]));
            mB = fmaxf(mB, fmaxf(acc[mi][ni][2], acc[mi][ni][3]));
        }
        mA = fmaxf(mA, __shfl_xor_sync(0xffffffff, mA, 1));
        mA = fmaxf(mA, __shfl_xor_sync(0xffffffff, mA, 2));
        mB = fmaxf(mB, __shfl_xor_sync(0xffffffff, mB, 1));
        mB = fmaxf(mB, __shfl_xor_sync(0xffffffff, mB, 2));
        float sA = 0.f, sB = 0.f;
        #pragma unroll
        for (int ni = 0; ni < 8; ni++) {
            float e0 = __expf(acc[mi][ni][0] - mA);
            float e1 = __expf(acc[mi][ni][1] - mA);
            float e2 = __expf(acc[mi][ni][2] - mB);
            float e3 = __expf(acc[mi][ni][3] - mB);
            acc[mi][ni][0] = e0; acc[mi][ni][1] = e1;
            acc[mi][ni][2] = e2; acc[mi][ni][3] = e3;
            sA += e0 + e1; sB += e2 + e3;
        }
        sA += __shfl_xor_sync(0xffffffff, sA, 1);
        sA += __shfl_xor_sync(0xffffffff, sA, 2);
        sB += __shfl_xor_sync(0xffffffff, sB, 1);
        sB += __shfl_xor_sync(0xffffffff, sB, 2);
        inv_[mi][0] = 1.f / sA;
        inv_[mi][1] = 1.f / sB;
    }

    // ---- store P (unnormalized, tf32) to smem; each warp owns its rows ----
    #pragma unroll
    for (int mi = 0; mi < 2; mi++) {
        const int r0 = warp * 32 + mi * 16 + g;
        #pragma unroll
        for (int ni = 0; ni < 8; ni++) {
            const int col = ni * 8 + 2 * tq;
            *(uint2*)(Ps_w + r0 * 68 + col) =
                make_uint2(f2tf(acc[mi][ni][0]), f2tf(acc[mi][ni][1]));
            *(uint2*)(Ps_w + (r0 + 8) * 68 + col) =
                make_uint2(f2tf(acc[mi][ni][2]), f2tf(acc[mi][ni][3]));
        }
    }
    __syncwarp();

    // ---- PV : warp tile 32(q) x 32(d), K=64 ----
    float o[2][4][4];
    #pragma unroll
    for (int mi = 0; mi < 2; mi++)
        #pragma unroll
        for (int ni = 0; ni < 4; ni++)
            #pragma unroll
            for (int j = 0; j < 4; j++) o[mi][ni][j] = 0.f;

    #pragma unroll
    for (int ks = 0; ks < 8; ks++) {
        uint32_t a0[2], a1[2], a2[2], a3[2];
        #pragma unroll
        for (int mi = 0; mi < 2; mi++) {
            const int r0 = warp * 32 + mi * 16 + g;
            a0[mi] = Ps_w[r0 * 68 + ks * 8 + tq];
            a1[mi] = Ps_w[(r0 + 8) * 68 + ks * 8 + tq];
            a2[mi] = Ps_w[r0 * 68 + ks * 8 + tq + 4];
            a3[mi] = Ps_w[(r0 + 8) * 68 + ks * 8 + tq + 4];
        }
        uint2 bv[4];
        #pragma unroll
        for (int ni = 0; ni < 4; ni++)
            bv[ni] = Vt2[(ni * 8 + g) * 33 + ks * 4 + tq];
        #pragma unroll
        for (int mi = 0; mi < 2; mi++)
            #pragma unroll
            for (int ni = 0; ni < 4; ni++)
                mma_tf32(o[mi][ni], a0[mi], a1[mi], a2[mi], a3[mi],
                         bv[ni].x, bv[ni].y);
    }

    // ---- normalize + store O ----
    #pragma unroll
    for (int mi = 0; mi < 2; mi++) {
        const int r = win * NQ + warp * 32 + mi * 16 + g;
        const float ivA = inv_[mi][0], ivB = inv_[mi][1];
        #pragma unroll
        for (int ni = 0; ni < 4; ni++) {
            const int col = h * HD + ni * 8 + 2 * tq;
            *(float2*)(g_att + (size_t)r * DIM + col) =
                make_float2(o[mi][ni][0] * ivA, o[mi][ni][1] * ivA);
            *(float2*)(g_att + (size_t)(r + 8) * DIM + col) =
                make_float2(o[mi][ni][2] * ivB, o[mi][ni][3] * ivB);
        }
    }
}

// ---------------------------------------------------------------------------
extern "C" void kernel_launch(void* const* d_in, const int* in_sizes, int n_in,
                              void* d_out, int out_size)
{
    const float* gauss = (const float*)d_in[0];
    const float* img   = (const float*)d_in[1];
    const float* btab  = (const float*)d_in[2];
    const float* Wq    = (const float*)d_in[3];
    const float* bq    = (const float*)d_in[4];
    const float* Wkv   = (const float*)d_in[5];
    const float* bkv   = (const float*)d_in[6];
    const float* Wp    = (const float*)d_in[7];
    const float* bp    = (const float*)d_in[8];
    float* out = (float*)d_out;

    void* pq = nullptr;   cudaGetSymbolAddress(&pq, g_q);
    void* pkv = nullptr;  cudaGetSymbolAddress(&pkv, g_kv);
    void* pa = nullptr;   cudaGetSymbolAddress(&pa, g_att);

    cudaFuncSetAttribute(attn_mma_kernel,
                         cudaFuncAttributeMaxDynamicSharedMemorySize, ATTN_SMEM_BYTES);

    // 1) Q projection
    gemm_tf32_kernel<false><<<dim3(DIM / 64, ROWS_Q / 128), 256>>>(gauss, Wq, bq, (float*)pq, DIM);
    // 2) KV projection (window gather fused)
    gemm_tf32_kernel<true><<<dim3((2 * DIM) / 64, ROWS_KV / 128), 256>>>(img, Wkv, bkv, (float*)pkv, 2 * DIM);
    // 3) Attention (tensor core)
    attn_mma_kernel<<<BW * HEADS, 256, ATTN_SMEM_BYTES>>>(btab);
    // 4) Output projection -> d_out
    gemm_tf32_kernel<false><<<dim3(DIM / 64, ROWS_Q / 128), 256>>>((const float*)pa, Wp, bp, out, DIM);
}

// round 7
// speedup vs baseline: 1.4756x; 1.3943x over previous
#include <cuda_runtime.h>
#include <cuda_fp16.h>
#include <cstdint>

#define WS    8
#define MQ    4
#define HEADS 8
#define DIM   256
#define HD    32
#define BATCH 4
#define IMGH  128
#define IMGW  128
#define NWIN  256
#define BW    (BATCH*NWIN)   // 1024 windows
#define WS2   64
#define NQ    (MQ*WS2)       // 256
#define ROWS_Q  (BW*NQ)      // 262144
#define ROWS_KV (BW*WS2)     // 65536

__device__ float g_q  [ROWS_Q  * DIM];
__device__ float g_kv [ROWS_KV * 2 * DIM];
__device__ float g_att[ROWS_Q  * DIM];

__device__ __forceinline__ uint32_t f2tf(float x) {
    uint32_t u;
    asm("cvt.rna.tf32.f32 %0, %1;" : "=r"(u) : "f"(x));
    return u;
}
__device__ __forceinline__ uint32_t pkh2(float a, float b) {
    __half2 h = __floats2half2_rn(a, b);
    return *(uint32_t*)&h;
}

__device__ __forceinline__ void mma_tf32(float c[4],
    uint32_t a0, uint32_t a1, uint32_t a2, uint32_t a3,
    uint32_t b0, uint32_t b1)
{
    asm volatile(
        "mma.sync.aligned.m16n8k8.row.col.f32.tf32.tf32.f32 "
        "{%0,%1,%2,%3}, {%4,%5,%6,%7}, {%8,%9}, {%0,%1,%2,%3};"
        : "+f"(c[0]), "+f"(c[1]), "+f"(c[2]), "+f"(c[3])
        : "r"(a0), "r"(a1), "r"(a2), "r"(a3), "r"(b0), "r"(b1));
}
__device__ __forceinline__ void mma_f16(float c[4],
    uint32_t a0, uint32_t a1, uint32_t a2, uint32_t a3,
    uint32_t b0, uint32_t b1)
{
    asm volatile(
        "mma.sync.aligned.m16n8k16.row.col.f32.f16.f16.f32 "
        "{%0,%1,%2,%3}, {%4,%5,%6,%7}, {%8,%9}, {%0,%1,%2,%3};"
        : "+f"(c[0]), "+f"(c[1]), "+f"(c[2]), "+f"(c[3])
        : "r"(a0), "r"(a1), "r"(a2), "r"(a3), "r"(b0), "r"(b1));
}

// ---------------------------------------------------------------------------
// fp16 GEMM (fp32 accum): C[M,N] = A[M,256] @ W[256,N] + bias[N]
// Block 128x64, BK=32, 8 warps (4x2), warp tile 32x32, mma.m16n8k16.
// Smem rows = 12 uint2 (24-word stride): 4-window bank tiling; per-row slot
// rotation makes BOTH staging stores and fragment loads conflict-free.
// uint2 slot tq holds {h2(k=2tq,2tq+1), h2(k=2tq+8,2tq+9)} of a k16 block.
// ---------------------------------------------------------------------------
template<bool GATHER>
__global__ __launch_bounds__(256) void gemm_f16_kernel(
    const float* __restrict__ A, const float* __restrict__ W,
    const float* __restrict__ bias, float* __restrict__ C, int N)
{
    __shared__ uint2 As2[128][12];   // [row][kb*4 + slot]
    __shared__ uint2 Wt2[64][12];    // [n]  [kb*4 + slot]
    uint32_t* Ws_w = (uint32_t*)Wt2; // word view, row stride 24

    const int t    = threadIdx.x;
    const int bm   = blockIdx.y, bn = blockIdx.x;
    const int lane = t & 31, warp = t >> 5;
    const int wm   = warp >> 1;      // 0..3
    const int wnn  = warp & 1;       // 0..1
    const int g    = lane >> 2;
    const int tq   = lane & 3;
    const int slot = (tq + ((g & 3) + 2 * (g >> 2))) & 3;   // load-side rotation

    // A stager: thread -> (row t>>1, k16-block t&1)
    const int arow = t >> 1, as_ = t & 1;
    const int rotA = ((arow & 3) + 2 * ((arow >> 2) & 1)) & 3;
    const float* Arow;
    if (GATHER) {
        const int r    = bm * 128 + arow;
        const int wwin = r >> 6, p = r & 63;
        const int b    = wwin >> 8, widx = wwin & 255;
        const int wy   = widx >> 4, wx = widx & 15;
        const int py   = wy * 8 + (p >> 3);
        const int px   = wx * 8 + (p & 7);
        Arow = A + (((size_t)b * IMGH + py) * IMGW + px) * DIM;
    } else {
        Arow = A + (size_t)(bm * 128 + arow) * DIM;
    }
    // W stager: thread -> (n = t>>2, k8-group kg = t&3)
    const int wn_ = t >> 2, wkg = t & 3;
    const int wkb = wkg >> 1, wp = wkg & 1;
    const int rotW = ((wn_ & 3) + 2 * ((wn_ >> 2) & 1)) & 3;
    const float* Wcol = W + bn * 64 + wn_;

    float acc[2][4][4];
    #pragma unroll
    for (int mi = 0; mi < 2; mi++)
        #pragma unroll
        for (int ni = 0; ni < 4; ni++)
            #pragma unroll
            for (int j = 0; j < 4; j++) acc[mi][ni][j] = 0.f;

    for (int k0 = 0; k0 < DIM; k0 += 32) {
        // ---- stage A: 16 floats of k16-block as_ ----
        {
            const float* ap = Arow + k0 + as_ * 16;
            float4 v0 = *(const float4*)(ap);
            float4 v1 = *(const float4*)(ap + 4);
            float4 v2 = *(const float4*)(ap + 8);
            float4 v3 = *(const float4*)(ap + 12);
            float f[16] = {v0.x,v0.y,v0.z,v0.w, v1.x,v1.y,v1.z,v1.w,
                           v2.x,v2.y,v2.z,v2.w, v3.x,v3.y,v3.z,v3.w};
            #pragma unroll
            for (int q = 0; q < 4; q++) {
                As2[arow][as_ * 4 + ((q + rotA) & 3)] =
                    make_uint2(pkh2(f[2*q], f[2*q+1]), pkh2(f[2*q+8], f[2*q+9]));
            }
        }
        // ---- stage W: 8 k-values of column wn_ ----
        {
            float wv[8];
            #pragma unroll
            for (int j = 0; j < 8; j++)
                wv[j] = Wcol[(size_t)(k0 + wkg * 8 + j) * N];
            #pragma unroll
            for (int q = 0; q < 4; q++) {
                Ws_w[wn_ * 24 + wkb * 8 + 2 * ((q + rotW) & 3) + wp] =
                    pkh2(wv[2*q], wv[2*q+1]);
            }
        }
        __syncthreads();

        #pragma unroll
        for (int kb = 0; kb < 2; kb++) {
            const int c = kb * 4 + slot;
            uint2 lo[2], hi[2];
            #pragma unroll
            for (int mi = 0; mi < 2; mi++) {
                const int r0 = wm * 32 + mi * 16 + g;
                lo[mi] = As2[r0][c];
                hi[mi] = As2[r0 + 8][c];
            }
            uint2 bf[4];
            #pragma unroll
            for (int ni = 0; ni < 4; ni++)
                bf[ni] = Wt2[wnn * 32 + ni * 8 + g][c];
            #pragma unroll
            for (int mi = 0; mi < 2; mi++)
                #pragma unroll
                for (int ni = 0; ni < 4; ni++)
                    mma_f16(acc[mi][ni], lo[mi].x, hi[mi].x, lo[mi].y, hi[mi].y,
                            bf[ni].x, bf[ni].y);
        }
        __syncthreads();
    }

    #pragma unroll
    for (int mi = 0; mi < 2; mi++) {
        const int r0 = bm * 128 + wm * 32 + mi * 16 + g;
        #pragma unroll
        for (int ni = 0; ni < 4; ni++) {
            const int col = bn * 64 + wnn * 32 + ni * 8 + 2 * tq;
            float2 bv = *(const float2*)(bias + col);
            float2 o0 = make_float2(acc[mi][ni][0] + bv.x, acc[mi][ni][1] + bv.y);
            float2 o1 = make_float2(acc[mi][ni][2] + bv.x, acc[mi][ni][3] + bv.y);
            *(float2*)(C + (size_t)r0 * N + col)       = o0;
            *(float2*)(C + (size_t)(r0 + 8) * N + col) = o1;
        }
    }
}

// ---------------------------------------------------------------------------
// Tensor-core attention (unchanged from R6). Block = (window, head).
// ---------------------------------------------------------------------------
#define ATTN_SMEM_BYTES 103424

__global__ __launch_bounds__(256) void attn_mma_kernel(const float* __restrict__ btab)
{
    extern __shared__ char smem[];
    uint32_t* Ps_w = (uint32_t*)smem;                       // [256][68]
    uint2*    Qs2  = (uint2*)smem;                          // [256][17]
    uint2*    Kt2  = (uint2*)(smem + 69632);                // [64][17]
    uint2*    Vt2  = (uint2*)(smem + 78336);                // [32][33]
    uint32_t* Vt_w = (uint32_t*)(smem + 78336);             // word view, stride 66
    float*    Bsf  = (float*)(smem + 86784);                // [64][65]

    const int blk = blockIdx.x;
    const int win = blk >> 3;
    const int h   = blk & 7;
    const int t   = threadIdx.x;
    const int lane = t & 31, warp = t >> 5;
    const int g   = lane >> 2;
    const int tq  = lane & 3;

    const float scale = 0.17677669529663687f;

    {
        const float* qp = g_q + ((size_t)(win * NQ + t)) * DIM + h * HD;
        #pragma unroll
        for (int s = 0; s < 4; s++) {
            float4 v0 = *(const float4*)(qp + s * 8);
            float4 v1 = *(const float4*)(qp + s * 8 + 4);
            Qs2[t * 17 + s * 4 + 0] = make_uint2(f2tf(v0.x * scale), f2tf(v1.x * scale));
            Qs2[t * 17 + s * 4 + 1] = make_uint2(f2tf(v0.y * scale), f2tf(v1.y * scale));
            Qs2[t * 17 + s * 4 + 2] = make_uint2(f2tf(v0.z * scale), f2tf(v1.z * scale));
            Qs2[t * 17 + s * 4 + 3] = make_uint2(f2tf(v0.w * scale), f2tf(v1.w * scale));
        }
    }
    if (t < 64) {
        const float* kp = g_kv + (size_t)(win * WS2 + t) * 512 + h * HD;
        #pragma unroll
        for (int s = 0; s < 4; s++) {
            float4 v0 = *(const float4*)(kp + s * 8);
            float4 v1 = *(const float4*)(kp + s * 8 + 4);
            Kt2[t * 17 + s * 4 + 0] = make_uint2(f2tf(v0.x), f2tf(v1.x));
            Kt2[t * 17 + s * 4 + 1] = make_uint2(f2tf(v0.y), f2tf(v1.y));
            Kt2[t * 17 + s * 4 + 2] = make_uint2(f2tf(v0.z), f2tf(v1.z));
            Kt2[t * 17 + s * 4 + 3] = make_uint2(f2tf(v0.w), f2tf(v1.w));
        }
    } else if (t < 128) {
        const int key = t - 64;
        const float* vp = g_kv + (size_t)(win * WS2 + key) * 512 + DIM + h * HD;
        const int s = key >> 3, within = key & 7;
        const int half = within >> 2, tqv = within & 3;
        const int cw = (s * 4 + tqv) * 2 + half;
        #pragma unroll
        for (int d = 0; d < 32; d += 4) {
            float4 v = *(const float4*)(vp + d);
            Vt_w[(d + 0) * 66 + cw] = f2tf(v.x);
            Vt_w[(d + 1) * 66 + cw] = f2tf(v.y);
            Vt_w[(d + 2) * 66 + cw] = f2tf(v.z);
            Vt_w[(d + 3) * 66 + cw] = f2tf(v.w);
        }
    }
    #pragma unroll
    for (int i = 0; i < 16; i++) {
        int e  = t + i * 256;
        int qp = e >> 6, kp = e & 63;
        int dr = (qp >> 3) - (kp >> 3) + 7;
        int dc = (qp & 7)  - (kp & 7)  + 7;
        Bsf[qp * 65 + kp] = btab[(dr * 15 + dc) * HEADS + h];
    }
    __syncthreads();

    float acc[2][8][4];
    #pragma unroll
    for (int mi = 0; mi < 2; mi++)
        #pragma unroll
        for (int ni = 0; ni < 8; ni++)
            #pragma unroll
            for (int j = 0; j < 4; j++) acc[mi][ni][j] = 0.f;

    #pragma unroll
    for (int ks = 0; ks < 4; ks++) {
        const int c = ks * 4 + tq;
        uint2 al[2], ah[2];
        #pragma unroll
        for (int mi = 0; mi < 2; mi++) {
            const int r0 = warp * 32 + mi * 16 + g;
            al[mi] = Qs2[r0 * 17 + c];
            ah[mi] = Qs2[(r0 + 8) * 17 + c];
        }
        uint2 bf[8];
        #pragma unroll
        for (int ni = 0; ni < 8; ni++)
            bf[ni] = Kt2[(ni * 8 + g) * 17 + c];
        #pragma unroll
        for (int mi = 0; mi < 2; mi++)
            #pragma unroll
            for (int ni = 0; ni < 8; ni++)
                mma_tf32(acc[mi][ni], al[mi].x, ah[mi].x, al[mi].y, ah[mi].y,
                         bf[ni].x, bf[ni].y);
    }
    __syncthreads();

    float inv_[2][2];
    #pragma unroll
    for (int mi = 0; mi < 2; mi++) {
        const int rA = warp * 32 + mi * 16 + g;
        const int qA = rA & 63, qB = (rA + 8) & 63;
        float mA = -1e30f, mB = -1e30f;
        #pragma unroll
        for (int ni = 0; ni < 8; ni++) {
            const int col = ni * 8 + 2 * tq;
            acc[mi][ni][0] += Bsf[qA * 65 + col];
            acc[mi][ni][1] += Bsf[qA * 65 + col + 1];
            acc[mi][ni][2] += Bsf[qB * 65 + col];
            acc[mi][ni][3] += Bsf[qB * 65 + col + 1];
            mA = fmaxf(mA, fmaxf(acc[mi][ni][0], acc[mi][ni][1]));
            mB = fmaxf(mB, fmaxf(acc[mi][ni][2], acc[mi][ni][3]));
        }
        mA = fmaxf(mA, __shfl_xor_sync(0xffffffff, mA, 1));
        mA = fmaxf(mA, __shfl_xor_sync(0xffffffff, mA, 2));
        mB = fmaxf(mB, __shfl_xor_sync(0xffffffff, mB, 1));
        mB = fmaxf(mB, __shfl_xor_sync(0xffffffff, mB, 2));
        float sA = 0.f, sB = 0.f;
        #pragma unroll
        for (int ni = 0; ni < 8; ni++) {
            float e0 = __expf(acc[mi][ni][0] - mA);
            float e1 = __expf(acc[mi][ni][1] - mA);
            float e2 = __expf(acc[mi][ni][2] - mB);
            float e3 = __expf(acc[mi][ni][3] - mB);
            acc[mi][ni][0] = e0; acc[mi][ni][1] = e1;
            acc[mi][ni][2] = e2; acc[mi][ni][3] = e3;
            sA += e0 + e1; sB += e2 + e3;
        }
        sA += __shfl_xor_sync(0xffffffff, sA, 1);
        sA += __shfl_xor_sync(0xffffffff, sA, 2);
        sB += __shfl_xor_sync(0xffffffff, sB, 1);
        sB += __shfl_xor_sync(0xffffffff, sB, 2);
        inv_[mi][0] = 1.f / sA;
        inv_[mi][1] = 1.f / sB;
    }

    #pragma unroll
    for (int mi = 0; mi < 2; mi++) {
        const int r0 = warp * 32 + mi * 16 + g;
        #pragma unroll
        for (int ni = 0; ni < 8; ni++) {
            const int col = ni * 8 + 2 * tq;
            *(uint2*)(Ps_w + r0 * 68 + col) =
                make_uint2(f2tf(acc[mi][ni][0]), f2tf(acc[mi][ni][1]));
            *(uint2*)(Ps_w + (r0 + 8) * 68 + col) =
                make_uint2(f2tf(acc[mi][ni][2]), f2tf(acc[mi][ni][3]));
        }
    }
    __syncwarp();

    float o[2][4][4];
    #pragma unroll
    for (int mi = 0; mi < 2; mi++)
        #pragma unroll
        for (int ni = 0; ni < 4; ni++)
            #pragma unroll
            for (int j = 0; j < 4; j++) o[mi][ni][j] = 0.f;

    #pragma unroll
    for (int ks = 0; ks < 8; ks++) {
        uint32_t a0[2], a1[2], a2[2], a3[2];
        #pragma unroll
        for (int mi = 0; mi < 2; mi++) {
            const int r0 = warp * 32 + mi * 16 + g;
            a0[mi] = Ps_w[r0 * 68 + ks * 8 + tq];
            a1[mi] = Ps_w[(r0 + 8) * 68 + ks * 8 + tq];
            a2[mi] = Ps_w[r0 * 68 + ks * 8 + tq + 4];
            a3[mi] = Ps_w[(r0 + 8) * 68 + ks * 8 + tq + 4];
        }
        uint2 bv[4];
        #pragma unroll
        for (int ni = 0; ni < 4; ni++)
            bv[ni] = Vt2[(ni * 8 + g) * 33 + ks * 4 + tq];
        #pragma unroll
        for (int mi = 0; mi < 2; mi++)
            #pragma unroll
            for (int ni = 0; ni < 4; ni++)
                mma_tf32(o[mi][ni], a0[mi], a1[mi], a2[mi], a3[mi],
                         bv[ni].x, bv[ni].y);
    }

    #pragma unroll
    for (int mi = 0; mi < 2; mi++) {
        const int r = win * NQ + warp * 32 + mi * 16 + g;
        const float ivA = inv_[mi][0], ivB = inv_[mi][1];
        #pragma unroll
        for (int ni = 0; ni < 4; ni++) {
            const int col = h * HD + ni * 8 + 2 * tq;
            *(float2*)(g_att + (size_t)r * DIM + col) =
                make_float2(o[mi][ni][0] * ivA, o[mi][ni][1] * ivA);
            *(float2*)(g_att + (size_t)(r + 8) * DIM + col) =
                make_float2(o[mi][ni][2] * ivB, o[mi][ni][3] * ivB);
        }
    }
}

// ---------------------------------------------------------------------------
extern "C" void kernel_launch(void* const* d_in, const int* in_sizes, int n_in,
                              void* d_out, int out_size)
{
    const float* gauss = (const float*)d_in[0];
    const float* img   = (const float*)d_in[1];
    const float* btab  = (const float*)d_in[2];
    const float* Wq    = (const float*)d_in[3];
    const float* bq    = (const float*)d_in[4];
    const float* Wkv   = (const float*)d_in[5];
    const float* bkv   = (const float*)d_in[6];
    const float* Wp    = (const float*)d_in[7];
    const float* bp    = (const float*)d_in[8];
    float* out = (float*)d_out;

    void* pq = nullptr;   cudaGetSymbolAddress(&pq, g_q);
    void* pkv = nullptr;  cudaGetSymbolAddress(&pkv, g_kv);
    void* pa = nullptr;   cudaGetSymbolAddress(&pa, g_att);

    cudaFuncSetAttribute(attn_mma_kernel,
                         cudaFuncAttributeMaxDynamicSharedMemorySize, ATTN_SMEM_BYTES);

    // 1) Q projection
    gemm_f16_kernel<false><<<dim3(DIM / 64, ROWS_Q / 128), 256>>>(gauss, Wq, bq, (float*)pq, DIM);
    // 2) KV projection (window gather fused)
    gemm_f16_kernel<true><<<dim3((2 * DIM) / 64, ROWS_KV / 128), 256>>>(img, Wkv, bkv, (float*)pkv, 2 * DIM);
    // 3) Attention (tensor core)
    attn_mma_kernel<<<BW * HEADS, 256, ATTN_SMEM_BYTES>>>(btab);
    // 4) Output projection -> d_out
    gemm_f16_kernel<false><<<dim3(DIM / 64, ROWS_Q / 128), 256>>>((const float*)pa, Wp, bp, out, DIM);
}

// round 8
// speedup vs baseline: 1.9991x; 1.3548x over previous
#include <cuda_runtime.h>
#include <cuda_fp16.h>
#include <cstdint>

#define WS    8
#define MQ    4
#define HEADS 8
#define DIM   256
#define HD    32
#define BATCH 4
#define IMGH  128
#define IMGW  128
#define NWIN  256
#define BW    (BATCH*NWIN)   // 1024 windows
#define WS2   64
#define NQ    (MQ*WS2)       // 256
#define ROWS_Q  (BW*NQ)      // 262144
#define ROWS_KV (BW*WS2)     // 65536

// fp16 intermediates (10-bit mantissa == tf32; no extra rounding vs R7 path)
__device__ __half g_q  [ROWS_Q  * DIM];        // 128 MB
__device__ __half g_kv [ROWS_KV * 2 * DIM];    // 64 MB
__device__ __half g_att[ROWS_Q  * DIM];        // 128 MB

__device__ __forceinline__ uint32_t pkh2(float a, float b) {
    __half2 h = __floats2half2_rn(a, b);
    return *(uint32_t*)&h;
}
__device__ __forceinline__ void mma_f16(float c[4],
    uint32_t a0, uint32_t a1, uint32_t a2, uint32_t a3,
    uint32_t b0, uint32_t b1)
{
    asm volatile(
        "mma.sync.aligned.m16n8k16.row.col.f32.f16.f16.f32 "
        "{%0,%1,%2,%3}, {%4,%5,%6,%7}, {%8,%9}, {%0,%1,%2,%3};"
        : "+f"(c[0]), "+f"(c[1]), "+f"(c[2]), "+f"(c[3])
        : "r"(a0), "r"(a1), "r"(a2), "r"(a3), "r"(b0), "r"(b1));
}

// ---------------------------------------------------------------------------
// fp16 GEMM (fp32 accum): C[M,N] = A[M,256] @ W[256,N] + bias[N]
// Block 128x64, BK=32, 8 warps (4x2), warp tile 32x32, mma.m16n8k16.
// Conflict-free rotated-slot smem layout (R7) + register-prefetch pipelining.
// AHALF: A rows are fp16 (g_att).  CHALF: C stored as fp16.
// ---------------------------------------------------------------------------
template<bool GATHER, bool AHALF, bool CHALF>
__global__ __launch_bounds__(256) void gemm_f16_kernel(
    const void* __restrict__ Av, const float* __restrict__ W,
    const float* __restrict__ bias, void* __restrict__ Cv, int N)
{
    __shared__ uint2 As2[128][12];   // [row][kb*4 + slot]
    __shared__ uint2 Wt2[64][12];    // [n]  [kb*4 + slot]
    uint32_t* Ws_w = (uint32_t*)Wt2; // word view, row stride 24

    const int t    = threadIdx.x;
    const int bm   = blockIdx.y, bn = blockIdx.x;
    const int lane = t & 31, warp = t >> 5;
    const int wm   = warp >> 1;
    const int wnn  = warp & 1;
    const int g    = lane >> 2;
    const int tq   = lane & 3;
    const int slot = (tq + ((g & 3) + 2 * (g >> 2))) & 3;

    // A stager: thread -> (row t>>1, k16-block t&1)
    const int arow = t >> 1, as_ = t & 1;
    const int rotA = ((arow & 3) + 2 * ((arow >> 2) & 1)) & 3;
    size_t aoff;
    if (GATHER) {
        const int r    = bm * 128 + arow;
        const int wwin = r >> 6, p = r & 63;
        const int b    = wwin >> 8, widx = wwin & 255;
        const int wy   = widx >> 4, wx = widx & 15;
        const int py   = wy * 8 + (p >> 3);
        const int px   = wx * 8 + (p & 7);
        aoff = (((size_t)b * IMGH + py) * IMGW + px) * DIM;
    } else {
        aoff = (size_t)(bm * 128 + arow) * DIM;
    }
    const float*  ArowF = (const float*)Av + aoff;
    const __half* ArowH = (const __half*)Av + aoff;

    // W stager: thread -> (n = t>>2, k8-group kg = t&3)
    const int wn_ = t >> 2, wkg = t & 3;
    const int wkb = wkg >> 1, wp = wkg & 1;
    const int rotW = ((wn_ & 3) + 2 * ((wn_ >> 2) & 1)) & 3;
    const float* Wcol = W + bn * 64 + wn_;

    float acc[2][4][4];
    #pragma unroll
    for (int mi = 0; mi < 2; mi++)
        #pragma unroll
        for (int ni = 0; ni < 4; ni++)
            #pragma unroll
            for (int j = 0; j < 4; j++) acc[mi][ni][j] = 0.f;

    // prefetch registers
    float    af[16];
    uint32_t aw[8];
    float    wvr[8];

    // ---- initial prefetch (k0 = 0) ----
    if (AHALF) {
        const uint4* ap = (const uint4*)(ArowH + as_ * 16);
        uint4 u0 = ap[0], u1 = ap[1];
        aw[0]=u0.x; aw[1]=u0.y; aw[2]=u0.z; aw[3]=u0.w;
        aw[4]=u1.x; aw[5]=u1.y; aw[6]=u1.z; aw[7]=u1.w;
    } else {
        const float* ap = ArowF + as_ * 16;
        float4 v0 = *(const float4*)(ap);
        float4 v1 = *(const float4*)(ap + 4);
        float4 v2 = *(const float4*)(ap + 8);
        float4 v3 = *(const float4*)(ap + 12);
        af[0]=v0.x; af[1]=v0.y; af[2]=v0.z; af[3]=v0.w;
        af[4]=v1.x; af[5]=v1.y; af[6]=v1.z; af[7]=v1.w;
        af[8]=v2.x; af[9]=v2.y; af[10]=v2.z; af[11]=v2.w;
        af[12]=v3.x; af[13]=v3.y; af[14]=v3.z; af[15]=v3.w;
    }
    #pragma unroll
    for (int j = 0; j < 8; j++)
        wvr[j] = Wcol[(size_t)(wkg * 8 + j) * N];

    for (int it = 0; it < 8; it++) {
        // ---- store staged regs to smem ----
        if (AHALF) {
            #pragma unroll
            for (int q = 0; q < 4; q++)
                As2[arow][as_ * 4 + ((q + rotA) & 3)] = make_uint2(aw[q], aw[q + 4]);
        } else {
            #pragma unroll
            for (int q = 0; q < 4; q++)
                As2[arow][as_ * 4 + ((q + rotA) & 3)] =
                    make_uint2(pkh2(af[2*q], af[2*q+1]), pkh2(af[2*q+8], af[2*q+9]));
        }
        #pragma unroll
        for (int q = 0; q < 4; q++)
            Ws_w[wn_ * 24 + wkb * 8 + 2 * ((q + rotW) & 3) + wp] =
                pkh2(wvr[2*q], wvr[2*q+1]);
        __syncthreads();

        // ---- prefetch next iteration while computing ----
        if (it < 7) {
            const int k0 = (it + 1) * 32;
            if (AHALF) {
                const uint4* ap = (const uint4*)(ArowH + k0 + as_ * 16);
                uint4 u0 = ap[0], u1 = ap[1];
                aw[0]=u0.x; aw[1]=u0.y; aw[2]=u0.z; aw[3]=u0.w;
                aw[4]=u1.x; aw[5]=u1.y; aw[6]=u1.z; aw[7]=u1.w;
            } else {
                const float* ap = ArowF + k0 + as_ * 16;
                float4 v0 = *(const float4*)(ap);
                float4 v1 = *(const float4*)(ap + 4);
                float4 v2 = *(const float4*)(ap + 8);
                float4 v3 = *(const float4*)(ap + 12);
                af[0]=v0.x; af[1]=v0.y; af[2]=v0.z; af[3]=v0.w;
                af[4]=v1.x; af[5]=v1.y; af[6]=v1.z; af[7]=v1.w;
                af[8]=v2.x; af[9]=v2.y; af[10]=v2.z; af[11]=v2.w;
                af[12]=v3.x; af[13]=v3.y; af[14]=v3.z; af[15]=v3.w;
            }
            #pragma unroll
            for (int j = 0; j < 8; j++)
                wvr[j] = Wcol[(size_t)(k0 + wkg * 8 + j) * N];
        }

        // ---- compute 2 k16 blocks ----
        #pragma unroll
        for (int kb = 0; kb < 2; kb++) {
            const int c = kb * 4 + slot;
            uint2 lo[2], hi[2];
            #pragma unroll
            for (int mi = 0; mi < 2; mi++) {
                const int r0 = wm * 32 + mi * 16 + g;
                lo[mi] = As2[r0][c];
                hi[mi] = As2[r0 + 8][c];
            }
            uint2 bf[4];
            #pragma unroll
            for (int ni = 0; ni < 4; ni++)
                bf[ni] = Wt2[wnn * 32 + ni * 8 + g][c];
            #pragma unroll
            for (int mi = 0; mi < 2; mi++)
                #pragma unroll
                for (int ni = 0; ni < 4; ni++)
                    mma_f16(acc[mi][ni], lo[mi].x, hi[mi].x, lo[mi].y, hi[mi].y,
                            bf[ni].x, bf[ni].y);
        }
        __syncthreads();
    }

    // ---- epilogue ----
    #pragma unroll
    for (int mi = 0; mi < 2; mi++) {
        const int r0 = bm * 128 + wm * 32 + mi * 16 + g;
        #pragma unroll
        for (int ni = 0; ni < 4; ni++) {
            const int col = bn * 64 + wnn * 32 + ni * 8 + 2 * tq;
            float2 bv = *(const float2*)(bias + col);
            float c0 = acc[mi][ni][0] + bv.x, c1 = acc[mi][ni][1] + bv.y;
            float c2 = acc[mi][ni][2] + bv.x, c3 = acc[mi][ni][3] + bv.y;
            if (CHALF) {
                __half* C = (__half*)Cv;
                *(uint32_t*)(C + (size_t)r0 * N + col)       = pkh2(c0, c1);
                *(uint32_t*)(C + (size_t)(r0 + 8) * N + col) = pkh2(c2, c3);
            } else {
                float* C = (float*)Cv;
                *(float2*)(C + (size_t)r0 * N + col)       = make_float2(c0, c1);
                *(float2*)(C + (size_t)(r0 + 8) * N + col) = make_float2(c2, c3);
            }
        }
    }
}

// ---------------------------------------------------------------------------
// fp16 tensor-core attention with register-resident P.
// Block = (window, head), 8 warps x 32 query rows, one __syncthreads total.
// Softmaxed QK^T accumulator fragments ARE the PV A-fragments (m16n8k16).
// Static smem ~43 KB.
// ---------------------------------------------------------------------------
__global__ __launch_bounds__(256) void attn_mma_kernel(const float* __restrict__ btab)
{
    __shared__ uint2  Qs2[256][12];    // Q rows, {h2(d2q,2q+1),h2(+8)} rotated slots
    __shared__ uint2  Kt2[64][12];     // K rows, same packing
    __shared__ __half Vt_h[32][72];    // V transposed: [d][key], stride 36 words
    __shared__ __half Bs_h[64][66];    // bias [q][key]

    const int blk = blockIdx.x;
    const int win = blk >> 3;
    const int h   = blk & 7;
    const int t   = threadIdx.x;
    const int lane = t & 31, warp = t >> 5;
    const int g   = lane >> 2;
    const int tq  = lane & 3;
    const int slot = (tq + ((g & 3) + 2 * (g >> 2))) & 3;

    // ---- stage Q: thread t -> query row t (32 halves = 2 k16 blocks) ----
    {
        const __half* qp = g_q + ((size_t)(win * NQ + t)) * DIM + h * HD;
        const int rot = ((t & 3) + 2 * ((t >> 2) & 1)) & 3;
        const uint4* qp4 = (const uint4*)qp;
        uint4 u0 = qp4[0], u1 = qp4[1], u2 = qp4[2], u3 = qp4[3];
        uint32_t w[16] = {u0.x,u0.y,u0.z,u0.w, u1.x,u1.y,u1.z,u1.w,
                          u2.x,u2.y,u2.z,u2.w, u3.x,u3.y,u3.z,u3.w};
        #pragma unroll
        for (int q = 0; q < 4; q++) {
            Qs2[t][((q + rot) & 3)]     = make_uint2(w[q],     w[q + 4]);
            Qs2[t][4 + ((q + rot) & 3)] = make_uint2(w[8 + q], w[12 + q]);
        }
    }
    // ---- stage K (threads 0..63) / V-transposed (threads 64..127) ----
    if (t < 64) {
        const __half* kp = g_kv + (size_t)(win * WS2 + t) * 512 + h * HD;
        const int rot = ((t & 3) + 2 * ((t >> 2) & 1)) & 3;
        const uint4* kp4 = (const uint4*)kp;
        uint4 u0 = kp4[0], u1 = kp4[1], u2 = kp4[2], u3 = kp4[3];
        uint32_t w[16] = {u0.x,u0.y,u0.z,u0.w, u1.x,u1.y,u1.z,u1.w,
                          u2.x,u2.y,u2.z,u2.w, u3.x,u3.y,u3.z,u3.w};
        #pragma unroll
        for (int q = 0; q < 4; q++) {
            Kt2[t][((q + rot) & 3)]     = make_uint2(w[q],     w[q + 4]);
            Kt2[t][4 + ((q + rot) & 3)] = make_uint2(w[8 + q], w[12 + q]);
        }
    } else if (t < 128) {
        const int key = t - 64;
        const __half2* vp2 = (const __half2*)(g_kv + (size_t)(win * WS2 + key) * 512
                                              + DIM + h * HD);
        #pragma unroll
        for (int j = 0; j < 16; j++) {
            __half2 v = vp2[j];
            Vt_h[2 * j][key]     = __low2half(v);
            Vt_h[2 * j + 1][key] = __high2half(v);
        }
    }
    // ---- stage bias (fp16) ----
    #pragma unroll
    for (int i = 0; i < 16; i++) {
        int e  = t + i * 256;
        int qp = e >> 6, kp = e & 63;
        int dr = (qp >> 3) - (kp >> 3) + 7;
        int dc = (qp & 7)  - (kp & 7)  + 7;
        Bs_h[qp][kp] = __float2half(btab[(dr * 15 + dc) * HEADS + h]);
    }
    __syncthreads();

    // ---- QK^T : warp tile 32(q) x 64(k), K=32 (2 k16 blocks) ----
    float acc[2][8][4];
    #pragma unroll
    for (int mi = 0; mi < 2; mi++)
        #pragma unroll
        for (int ni = 0; ni < 8; ni++)
            #pragma unroll
            for (int j = 0; j < 4; j++) acc[mi][ni][j] = 0.f;

    #pragma unroll
    for (int kb = 0; kb < 2; kb++) {
        const int c = kb * 4 + slot;
        uint2 lo[2], hi[2];
        #pragma unroll
        for (int mi = 0; mi < 2; mi++) {
            const int r0 = warp * 32 + mi * 16 + g;
            lo[mi] = Qs2[r0][c];
            hi[mi] = Qs2[r0 + 8][c];
        }
        uint2 bf[8];
        #pragma unroll
        for (int ni = 0; ni < 8; ni++)
            bf[ni] = Kt2[ni * 8 + g][c];
        #pragma unroll
        for (int mi = 0; mi < 2; mi++)
            #pragma unroll
            for (int ni = 0; ni < 8; ni++)
                mma_f16(acc[mi][ni], lo[mi].x, hi[mi].x, lo[mi].y, hi[mi].y,
                        bf[ni].x, bf[ni].y);
    }

    // ---- scale + bias + softmax (per accumulator row) ----
    const float scale = 0.17677669529663687f;  // 32^-0.5
    float inv_[2][2];
    #pragma unroll
    for (int mi = 0; mi < 2; mi++) {
        const int rA = warp * 32 + mi * 16 + g;
        const int qA = rA & 63, qB = (rA + 8) & 63;
        float mA = -1e30f, mB = -1e30f;
        #pragma unroll
        for (int ni = 0; ni < 8; ni++) {
            const int col = ni * 8 + 2 * tq;
            float2 bA = __half22float2(*(const __half2*)&Bs_h[qA][col]);
            float2 bB = __half22float2(*(const __half2*)&Bs_h[qB][col]);
            acc[mi][ni][0] = acc[mi][ni][0] * scale + bA.x;
            acc[mi][ni][1] = acc[mi][ni][1] * scale + bA.y;
            acc[mi][ni][2] = acc[mi][ni][2] * scale + bB.x;
            acc[mi][ni][3] = acc[mi][ni][3] * scale + bB.y;
            mA = fmaxf(mA, fmaxf(acc[mi][ni][0], acc[mi][ni][1]));
            mB = fmaxf(mB, fmaxf(acc[mi][ni][2], acc[mi][ni][3]));
        }
        mA = fmaxf(mA, __shfl_xor_sync(0xffffffff, mA, 1));
        mA = fmaxf(mA, __shfl_xor_sync(0xffffffff, mA, 2));
        mB = fmaxf(mB, __shfl_xor_sync(0xffffffff, mB, 1));
        mB = fmaxf(mB, __shfl_xor_sync(0xffffffff, mB, 2));
        float sA = 0.f, sB = 0.f;
        #pragma unroll
        for (int ni = 0; ni < 8; ni++) {
            float e0 = __expf(acc[mi][ni][0] - mA);
            float e1 = __expf(acc[mi][ni][1] - mA);
            float e2 = __expf(acc[mi][ni][2] - mB);
            float e3 = __expf(acc[mi][ni][3] - mB);
            acc[mi][ni][0] = e0; acc[mi][ni][1] = e1;
            acc[mi][ni][2] = e2; acc[mi][ni][3] = e3;
            sA += e0 + e1; sB += e2 + e3;
        }
        sA += __shfl_xor_sync(0xffffffff, sA, 1);
        sA += __shfl_xor_sync(0xffffffff, sA, 2);
        sB += __shfl_xor_sync(0xffffffff, sB, 1);
        sB += __shfl_xor_sync(0xffffffff, sB, 2);
        inv_[mi][0] = 1.f / sA;
        inv_[mi][1] = 1.f / sB;
    }

    // ---- PV : P stays in registers (acc fragments == A-fragments) ----
    float o[2][4][4];
    #pragma unroll
    for (int mi = 0; mi < 2; mi++)
        #pragma unroll
        for (int ni = 0; ni < 4; ni++)
            #pragma unroll
            for (int j = 0; j < 4; j++) o[mi][ni][j] = 0.f;

    #pragma unroll
    for (int kb = 0; kb < 4; kb++) {
        uint32_t a0[2], a1[2], a2[2], a3[2];
        #pragma unroll
        for (int mi = 0; mi < 2; mi++) {
            a0[mi] = pkh2(acc[mi][2*kb][0],     acc[mi][2*kb][1]);
            a1[mi] = pkh2(acc[mi][2*kb][2],     acc[mi][2*kb][3]);
            a2[mi] = pkh2(acc[mi][2*kb+1][0],   acc[mi][2*kb+1][1]);
            a3[mi] = pkh2(acc[mi][2*kb+1][2],   acc[mi][2*kb+1][3]);
        }
        #pragma unroll
        for (int ni = 0; ni < 4; ni++) {
            const __half* vrow = &Vt_h[ni * 8 + g][0];
            uint32_t b0 = *(const uint32_t*)(vrow + 16 * kb + 2 * tq);
            uint32_t b1 = *(const uint32_t*)(vrow + 16 * kb + 8 + 2 * tq);
            #pragma unroll
            for (int mi = 0; mi < 2; mi++)
                mma_f16(o[mi][ni], a0[mi], a1[mi], a2[mi], a3[mi], b0, b1);
        }
    }

    // ---- normalize + store O (fp16) ----
    #pragma unroll
    for (int mi = 0; mi < 2; mi++) {
        const int r = win * NQ + warp * 32 + mi * 16 + g;
        const float ivA = inv_[mi][0], ivB = inv_[mi][1];
        #pragma unroll
        for (int ni = 0; ni < 4; ni++) {
            const int col = h * HD + ni * 8 + 2 * tq;
            *(uint32_t*)(g_att + (size_t)r * DIM + col) =
                pkh2(o[mi][ni][0] * ivA, o[mi][ni][1] * ivA);
            *(uint32_t*)(g_att + (size_t)(r + 8) * DIM + col) =
                pkh2(o[mi][ni][2] * ivB, o[mi][ni][3] * ivB);
        }
    }
}

// ---------------------------------------------------------------------------
extern "C" void kernel_launch(void* const* d_in, const int* in_sizes, int n_in,
                              void* d_out, int out_size)
{
    const float* gauss = (const float*)d_in[0];
    const float* img   = (const float*)d_in[1];
    const float* btab  = (const float*)d_in[2];
    const float* Wq    = (const float*)d_in[3];
    const float* bq    = (const float*)d_in[4];
    const float* Wkv   = (const float*)d_in[5];
    const float* bkv   = (const float*)d_in[6];
    const float* Wp    = (const float*)d_in[7];
    const float* bp    = (const float*)d_in[8];
    float* out = (float*)d_out;

    void* pq = nullptr;   cudaGetSymbolAddress(&pq, g_q);
    void* pkv = nullptr;  cudaGetSymbolAddress(&pkv, g_kv);
    void* pa = nullptr;   cudaGetSymbolAddress(&pa, g_att);

    // 1) Q projection: fp32 A (gauss) -> fp16 C (g_q)
    gemm_f16_kernel<false, false, true>
        <<<dim3(DIM / 64, ROWS_Q / 128), 256>>>(gauss, Wq, bq, pq, DIM);
    // 2) KV projection (window gather): fp32 A (img) -> fp16 C (g_kv)
    gemm_f16_kernel<true, false, true>
        <<<dim3((2 * DIM) / 64, ROWS_KV / 128), 256>>>(img, Wkv, bkv, pkv, 2 * DIM);
    // 3) Attention (fp16 MMA, register-resident P)
    attn_mma_kernel<<<BW * HEADS, 256>>>(btab);
    // 4) Output projection: fp16 A (g_att) -> fp32 C (d_out)
    gemm_f16_kernel<false, true, false>
        <<<dim3(DIM / 64, ROWS_Q / 128), 256>>>(pa, Wp, bp, out, DIM);
}

// round 9
// speedup vs baseline: 2.5188x; 1.2599x over previous
#include <cuda_runtime.h>
#include <cuda_fp16.h>
#include <cstdint>

#define WS    8
#define MQ    4
#define HEADS 8
#define DIM   256
#define HD    32
#define BATCH 4
#define IMGH  128
#define IMGW  128
#define NWIN  256
#define BW    (BATCH*NWIN)   // 1024 windows
#define WS2   64
#define NQ    (MQ*WS2)       // 256
#define ROWS_Q  (BW*NQ)      // 262144
#define ROWS_KV (BW*WS2)     // 65536

__device__ __half g_q  [ROWS_Q  * DIM];
__device__ __half g_kv [ROWS_KV * 2 * DIM];
__device__ __half g_att[ROWS_Q  * DIM];

__device__ __forceinline__ uint32_t pkh2(float a, float b) {
    __half2 h = __floats2half2_rn(a, b);
    return *(uint32_t*)&h;
}
__device__ __forceinline__ void mma_f16(float c[4],
    uint32_t a0, uint32_t a1, uint32_t a2, uint32_t a3,
    uint32_t b0, uint32_t b1)
{
    asm volatile(
        "mma.sync.aligned.m16n8k16.row.col.f32.f16.f16.f32 "
        "{%0,%1,%2,%3}, {%4,%5,%6,%7}, {%8,%9}, {%0,%1,%2,%3};"
        : "+f"(c[0]), "+f"(c[1]), "+f"(c[2]), "+f"(c[3])
        : "r"(a0), "r"(a1), "r"(a2), "r"(a3), "r"(b0), "r"(b1));
}

// ---------------------------------------------------------------------------
// fp16 GEMM (fp32 accum): C[M,N] = A[M,256] @ W[256,N] + bias[N]
// Block 128x128, BK=32, 8 warps (4x2), warp tile 32x64, mma.m16n8k16.
// Conflict-free rotated-slot smem layout; register prefetch (packed at load).
// ---------------------------------------------------------------------------
template<bool GATHER, bool AHALF, bool CHALF>
__global__ __launch_bounds__(256, 2) void gemm_f16_kernel(
    const void* __restrict__ Av, const float* __restrict__ W,
    const float* __restrict__ bias, void* __restrict__ Cv, int N)
{
    __shared__ uint2 As2[128][12];   // [row][kb*4 + slot]
    __shared__ uint2 Wt2[128][12];   // [n]  [kb*4 + slot]

    const int t    = threadIdx.x;
    const int bm   = blockIdx.y, bn = blockIdx.x;
    const int lane = t & 31, warp = t >> 5;
    const int wm   = warp >> 1;      // 0..3 : 32-row strip
    const int wnn  = warp & 1;       // 0..1 : 64-col strip
    const int g    = lane >> 2;
    const int tq   = lane & 3;
    const int slot = (tq + ((g & 3) + 2 * (g >> 2))) & 3;

    // A stager: thread -> (row t>>1, k16-block t&1)
    const int arow = t >> 1, as_ = t & 1;
    const int rotA = ((arow & 3) + 2 * ((arow >> 2) & 1)) & 3;
    size_t aoff;
    if (GATHER) {
        const int r    = bm * 128 + arow;
        const int wwin = r >> 6, p = r & 63;
        const int b    = wwin >> 8, widx = wwin & 255;
        const int wy   = widx >> 4, wx = widx & 15;
        const int py   = wy * 8 + (p >> 3);
        const int px   = wx * 8 + (p & 7);
        aoff = (((size_t)b * IMGH + py) * IMGW + px) * DIM;
    } else {
        aoff = (size_t)(bm * 128 + arow) * DIM;
    }
    const float*  ArowF = (const float*)Av + aoff;
    const __half* ArowH = (const __half*)Av + aoff;

    // W stager: same mapping as A stager -> (col n = t>>1, k16-block t&1)
    const int wn_ = t >> 1, kbw = t & 1;
    const int rotW = ((wn_ & 3) + 2 * ((wn_ >> 2) & 1)) & 3;
    const float* Wcol = W + bn * 128 + wn_;

    float acc[2][8][4];
    #pragma unroll
    for (int mi = 0; mi < 2; mi++)
        #pragma unroll
        for (int ni = 0; ni < 8; ni++)
            #pragma unroll
            for (int j = 0; j < 4; j++) acc[mi][ni][j] = 0.f;

    // prefetch (packed): apk[q] = h2(k=2q,2q+1), apk[q+4] = h2(k=2q+8,2q+9)
    uint32_t apk[8], wpk[8];

    // ---- initial prefetch (k0 = 0) ----
    if (AHALF) {
        const uint4* ap = (const uint4*)(ArowH + as_ * 16);
        uint4 u0 = ap[0], u1 = ap[1];
        apk[0]=u0.x; apk[1]=u0.y; apk[2]=u0.z; apk[3]=u0.w;
        apk[4]=u1.x; apk[5]=u1.y; apk[6]=u1.z; apk[7]=u1.w;
    } else {
        const float* ap = ArowF + as_ * 16;
        float4 v0 = *(const float4*)(ap);
        float4 v1 = *(const float4*)(ap + 4);
        float4 v2 = *(const float4*)(ap + 8);
        float4 v3 = *(const float4*)(ap + 12);
        apk[0]=pkh2(v0.x,v0.y); apk[1]=pkh2(v0.z,v0.w);
        apk[2]=pkh2(v1.x,v1.y); apk[3]=pkh2(v1.z,v1.w);
        apk[4]=pkh2(v2.x,v2.y); apk[5]=pkh2(v2.z,v2.w);
        apk[6]=pkh2(v3.x,v3.y); apk[7]=pkh2(v3.z,v3.w);
    }
    #pragma unroll
    for (int q = 0; q < 8; q++) {
        float w0 = Wcol[(size_t)(kbw * 16 + 2*q)     * N];
        float w1 = Wcol[(size_t)(kbw * 16 + 2*q + 1) * N];
        wpk[q] = pkh2(w0, w1);
    }

    for (int it = 0; it < 8; it++) {
        // ---- store staged regs to smem ----
        #pragma unroll
        for (int q = 0; q < 4; q++)
            As2[arow][as_ * 4 + ((q + rotA) & 3)] = make_uint2(apk[q], apk[q + 4]);
        #pragma unroll
        for (int q = 0; q < 4; q++)
            Wt2[wn_][kbw * 4 + ((q + rotW) & 3)] = make_uint2(wpk[q], wpk[q + 4]);
        __syncthreads();

        // ---- prefetch next iteration ----
        if (it < 7) {
            const int k0 = (it + 1) * 32;
            if (AHALF) {
                const uint4* ap = (const uint4*)(ArowH + k0 + as_ * 16);
                uint4 u0 = ap[0], u1 = ap[1];
                apk[0]=u0.x; apk[1]=u0.y; apk[2]=u0.z; apk[3]=u0.w;
                apk[4]=u1.x; apk[5]=u1.y; apk[6]=u1.z; apk[7]=u1.w;
            } else {
                const float* ap = ArowF + k0 + as_ * 16;
                float4 v0 = *(const float4*)(ap);
                float4 v1 = *(const float4*)(ap + 4);
                float4 v2 = *(const float4*)(ap + 8);
                float4 v3 = *(const float4*)(ap + 12);
                apk[0]=pkh2(v0.x,v0.y); apk[1]=pkh2(v0.z,v0.w);
                apk[2]=pkh2(v1.x,v1.y); apk[3]=pkh2(v1.z,v1.w);
                apk[4]=pkh2(v2.x,v2.y); apk[5]=pkh2(v2.z,v2.w);
                apk[6]=pkh2(v3.x,v3.y); apk[7]=pkh2(v3.z,v3.w);
            }
            #pragma unroll
            for (int q = 0; q < 8; q++) {
                float w0 = Wcol[(size_t)(k0 + kbw * 16 + 2*q)     * N];
                float w1 = Wcol[(size_t)(k0 + kbw * 16 + 2*q + 1) * N];
                wpk[q] = pkh2(w0, w1);
            }
        }

        // ---- compute 2 k16 blocks ----
        #pragma unroll
        for (int kb = 0; kb < 2; kb++) {
            const int c = kb * 4 + slot;
            uint2 lo[2], hi[2];
            #pragma unroll
            for (int mi = 0; mi < 2; mi++) {
                const int r0 = wm * 32 + mi * 16 + g;
                lo[mi] = As2[r0][c];
                hi[mi] = As2[r0 + 8][c];
            }
            uint2 bf[8];
            #pragma unroll
            for (int ni = 0; ni < 8; ni++)
                bf[ni] = Wt2[wnn * 64 + ni * 8 + g][c];
            #pragma unroll
            for (int mi = 0; mi < 2; mi++)
                #pragma unroll
                for (int ni = 0; ni < 8; ni++)
                    mma_f16(acc[mi][ni], lo[mi].x, hi[mi].x, lo[mi].y, hi[mi].y,
                            bf[ni].x, bf[ni].y);
        }
        __syncthreads();
    }

    // ---- epilogue ----
    #pragma unroll
    for (int mi = 0; mi < 2; mi++) {
        const int r0 = bm * 128 + wm * 32 + mi * 16 + g;
        #pragma unroll
        for (int ni = 0; ni < 8; ni++) {
            const int col = bn * 128 + wnn * 64 + ni * 8 + 2 * tq;
            float2 bv = *(const float2*)(bias + col);
            float c0 = acc[mi][ni][0] + bv.x, c1 = acc[mi][ni][1] + bv.y;
            float c2 = acc[mi][ni][2] + bv.x, c3 = acc[mi][ni][3] + bv.y;
            if (CHALF) {
                __half* C = (__half*)Cv;
                *(uint32_t*)(C + (size_t)r0 * N + col)       = pkh2(c0, c1);
                *(uint32_t*)(C + (size_t)(r0 + 8) * N + col) = pkh2(c2, c3);
            } else {
                float* C = (float*)Cv;
                *(float2*)(C + (size_t)r0 * N + col)       = make_float2(c0, c1);
                *(float2*)(C + (size_t)(r0 + 8) * N + col) = make_float2(c2, c3);
            }
        }
    }
}

// ---------------------------------------------------------------------------
// fp16 tensor-core attention with register-resident P (unchanged from R8).
// ---------------------------------------------------------------------------
__global__ __launch_bounds__(256) void attn_mma_kernel(const float* __restrict__ btab)
{
    __shared__ uint2  Qs2[256][12];
    __shared__ uint2  Kt2[64][12];
    __shared__ __half Vt_h[32][72];
    __shared__ __half Bs_h[64][66];

    const int blk = blockIdx.x;
    const int win = blk >> 3;
    const int h   = blk & 7;
    const int t   = threadIdx.x;
    const int lane = t & 31, warp = t >> 5;
    const int g   = lane >> 2;
    const int tq  = lane & 3;
    const int slot = (tq + ((g & 3) + 2 * (g >> 2))) & 3;

    {
        const __half* qp = g_q + ((size_t)(win * NQ + t)) * DIM + h * HD;
        const int rot = ((t & 3) + 2 * ((t >> 2) & 1)) & 3;
        const uint4* qp4 = (const uint4*)qp;
        uint4 u0 = qp4[0], u1 = qp4[1], u2 = qp4[2], u3 = qp4[3];
        uint32_t w[16] = {u0.x,u0.y,u0.z,u0.w, u1.x,u1.y,u1.z,u1.w,
                          u2.x,u2.y,u2.z,u2.w, u3.x,u3.y,u3.z,u3.w};
        #pragma unroll
        for (int q = 0; q < 4; q++) {
            Qs2[t][((q + rot) & 3)]     = make_uint2(w[q],     w[q + 4]);
            Qs2[t][4 + ((q + rot) & 3)] = make_uint2(w[8 + q], w[12 + q]);
        }
    }
    if (t < 64) {
        const __half* kp = g_kv + (size_t)(win * WS2 + t) * 512 + h * HD;
        const int rot = ((t & 3) + 2 * ((t >> 2) & 1)) & 3;
        const uint4* kp4 = (const uint4*)kp;
        uint4 u0 = kp4[0], u1 = kp4[1], u2 = kp4[2], u3 = kp4[3];
        uint32_t w[16] = {u0.x,u0.y,u0.z,u0.w, u1.x,u1.y,u1.z,u1.w,
                          u2.x,u2.y,u2.z,u2.w, u3.x,u3.y,u3.z,u3.w};
        #pragma unroll
        for (int q = 0; q < 4; q++) {
            Kt2[t][((q + rot) & 3)]     = make_uint2(w[q],     w[q + 4]);
            Kt2[t][4 + ((q + rot) & 3)] = make_uint2(w[8 + q], w[12 + q]);
        }
    } else if (t < 128) {
        const int key = t - 64;
        const __half2* vp2 = (const __half2*)(g_kv + (size_t)(win * WS2 + key) * 512
                                              + DIM + h * HD);
        #pragma unroll
        for (int j = 0; j < 16; j++) {
            __half2 v = vp2[j];
            Vt_h[2 * j][key]     = __low2half(v);
            Vt_h[2 * j + 1][key] = __high2half(v);
        }
    }
    #pragma unroll
    for (int i = 0; i < 16; i++) {
        int e  = t + i * 256;
        int qp = e >> 6, kp = e & 63;
        int dr = (qp >> 3) - (kp >> 3) + 7;
        int dc = (qp & 7)  - (kp & 7)  + 7;
        Bs_h[qp][kp] = __float2half(btab[(dr * 15 + dc) * HEADS + h]);
    }
    __syncthreads();

    float acc[2][8][4];
    #pragma unroll
    for (int mi = 0; mi < 2; mi++)
        #pragma unroll
        for (int ni = 0; ni < 8; ni++)
            #pragma unroll
            for (int j = 0; j < 4; j++) acc[mi][ni][j] = 0.f;

    #pragma unroll
    for (int kb = 0; kb < 2; kb++) {
        const int c = kb * 4 + slot;
        uint2 lo[2], hi[2];
        #pragma unroll
        for (int mi = 0; mi < 2; mi++) {
            const int r0 = warp * 32 + mi * 16 + g;
            lo[mi] = Qs2[r0][c];
            hi[mi] = Qs2[r0 + 8][c];
        }
        uint2 bf[8];
        #pragma unroll
        for (int ni = 0; ni < 8; ni++)
            bf[ni] = Kt2[ni * 8 + g][c];
        #pragma unroll
        for (int mi = 0; mi < 2; mi++)
            #pragma unroll
            for (int ni = 0; ni < 8; ni++)
                mma_f16(acc[mi][ni], lo[mi].x, hi[mi].x, lo[mi].y, hi[mi].y,
                        bf[ni].x, bf[ni].y);
    }

    const float scale = 0.17677669529663687f;
    float inv_[2][2];
    #pragma unroll
    for (int mi = 0; mi < 2; mi++) {
        const int rA = warp * 32 + mi * 16 + g;
        const int qA = rA & 63, qB = (rA + 8) & 63;
        float mA = -1e30f, mB = -1e30f;
        #pragma unroll
        for (int ni = 0; ni < 8; ni++) {
            const int col = ni * 8 + 2 * tq;
            float2 bA = __half22float2(*(const __half2*)&Bs_h[qA][col]);
            float2 bB = __half22float2(*(const __half2*)&Bs_h[qB][col]);
            acc[mi][ni][0] = acc[mi][ni][0] * scale + bA.x;
            acc[mi][ni][1] = acc[mi][ni][1] * scale + bA.y;
            acc[mi][ni][2] = acc[mi][ni][2] * scale + bB.x;
            acc[mi][ni][3] = acc[mi][ni][3] * scale + bB.y;
            mA = fmaxf(mA, fmaxf(acc[mi][ni][0], acc[mi][ni][1]));
            mB = fmaxf(mB, fmaxf(acc[mi][ni][2], acc[mi][ni][3]));
        }
        mA = fmaxf(mA, __shfl_xor_sync(0xffffffff, mA, 1));
        mA = fmaxf(mA, __shfl_xor_sync(0xffffffff, mA, 2));
        mB = fmaxf(mB, __shfl_xor_sync(0xffffffff, mB, 1));
        mB = fmaxf(mB, __shfl_xor_sync(0xffffffff, mB, 2));
        float sA = 0.f, sB = 0.f;
        #pragma unroll
        for (int ni = 0; ni < 8; ni++) {
            float e0 = __expf(acc[mi][ni][0] - mA);
            float e1 = __expf(acc[mi][ni][1] - mA);
            float e2 = __expf(acc[mi][ni][2] - mB);
            float e3 = __expf(acc[mi][ni][3] - mB);
            acc[mi][ni][0] = e0; acc[mi][ni][1] = e1;
            acc[mi][ni][2] = e2; acc[mi][ni][3] = e3;
            sA += e0 + e1; sB += e2 + e3;
        }
        sA += __shfl_xor_sync(0xffffffff, sA, 1);
        sA += __shfl_xor_sync(0xffffffff, sA, 2);
        sB += __shfl_xor_sync(0xffffffff, sB, 1);
        sB += __shfl_xor_sync(0xffffffff, sB, 2);
        inv_[mi][0] = 1.f / sA;
        inv_[mi][1] = 1.f / sB;
    }

    float o[2][4][4];
    #pragma unroll
    for (int mi = 0; mi < 2; mi++)
        #pragma unroll
        for (int ni = 0; ni < 4; ni++)
            #pragma unroll
            for (int j = 0; j < 4; j++) o[mi][ni][j] = 0.f;

    #pragma unroll
    for (int kb = 0; kb < 4; kb++) {
        uint32_t a0[2], a1[2], a2[2], a3[2];
        #pragma unroll
        for (int mi = 0; mi < 2; mi++) {
            a0[mi] = pkh2(acc[mi][2*kb][0],     acc[mi][2*kb][1]);
            a1[mi] = pkh2(acc[mi][2*kb][2],     acc[mi][2*kb][3]);
            a2[mi] = pkh2(acc[mi][2*kb+1][0],   acc[mi][2*kb+1][1]);
            a3[mi] = pkh2(acc[mi][2*kb+1][2],   acc[mi][2*kb+1][3]);
        }
        #pragma unroll
        for (int ni = 0; ni < 4; ni++) {
            const __half* vrow = &Vt_h[ni * 8 + g][0];
            uint32_t b0 = *(const uint32_t*)(vrow + 16 * kb + 2 * tq);
            uint32_t b1 = *(const uint32_t*)(vrow + 16 * kb + 8 + 2 * tq);
            #pragma unroll
            for (int mi = 0; mi < 2; mi++)
                mma_f16(o[mi][ni], a0[mi], a1[mi], a2[mi], a3[mi], b0, b1);
        }
    }

    #pragma unroll
    for (int mi = 0; mi < 2; mi++) {
        const int r = win * NQ + warp * 32 + mi * 16 + g;
        const float ivA = inv_[mi][0], ivB = inv_[mi][1];
        #pragma unroll
        for (int ni = 0; ni < 4; ni++) {
            const int col = h * HD + ni * 8 + 2 * tq;
            *(uint32_t*)(g_att + (size_t)r * DIM + col) =
                pkh2(o[mi][ni][0] * ivA, o[mi][ni][1] * ivA);
            *(uint32_t*)(g_att + (size_t)(r + 8) * DIM + col) =
                pkh2(o[mi][ni][2] * ivB, o[mi][ni][3] * ivB);
        }
    }
}

// ---------------------------------------------------------------------------
extern "C" void kernel_launch(void* const* d_in, const int* in_sizes, int n_in,
                              void* d_out, int out_size)
{
    const float* gauss = (const float*)d_in[0];
    const float* img   = (const float*)d_in[1];
    const float* btab  = (const float*)d_in[2];
    const float* Wq    = (const float*)d_in[3];
    const float* bq    = (const float*)d_in[4];
    const float* Wkv   = (const float*)d_in[5];
    const float* bkv   = (const float*)d_in[6];
    const float* Wp    = (const float*)d_in[7];
    const float* bp    = (const float*)d_in[8];
    float* out = (float*)d_out;

    void* pq = nullptr;   cudaGetSymbolAddress(&pq, g_q);
    void* pkv = nullptr;  cudaGetSymbolAddress(&pkv, g_kv);
    void* pa = nullptr;   cudaGetSymbolAddress(&pa, g_att);

    // 1) Q projection: fp32 A -> fp16 C
    gemm_f16_kernel<false, false, true>
        <<<dim3(DIM / 128, ROWS_Q / 128), 256>>>(gauss, Wq, bq, pq, DIM);
    // 2) KV projection (window gather): fp32 A -> fp16 C
    gemm_f16_kernel<true, false, true>
        <<<dim3((2 * DIM) / 128, ROWS_KV / 128), 256>>>(img, Wkv, bkv, pkv, 2 * DIM);
    // 3) Attention (fp16 MMA, register-resident P)
    attn_mma_kernel<<<BW * HEADS, 256>>>(btab);
    // 4) Output projection: fp16 A -> fp32 C (d_out)
    gemm_f16_kernel<false, true, false>
        <<<dim3(DIM / 128, ROWS_Q / 128), 256>>>(pa, Wp, bp, out, DIM);
}

// round 10
// speedup vs baseline: 2.5738x; 1.0219x over previous
#include <cuda_runtime.h>
#include <cuda_fp16.h>
#include <cstdint>

#define WS    8
#define MQ    4
#define HEADS 8
#define DIM   256
#define HD    32
#define BATCH 4
#define IMGH  128
#define IMGW  128
#define NWIN  256
#define BW    (BATCH*NWIN)   // 1024 windows
#define WS2   64
#define NQ    (MQ*WS2)       // 256
#define ROWS_Q  (BW*NQ)      // 262144
#define ROWS_KV (BW*WS2)     // 65536

__device__ __half g_q  [ROWS_Q  * DIM];
__device__ __half g_kv [ROWS_KV * 2 * DIM];
__device__ __half g_att[ROWS_Q  * DIM];

__device__ __forceinline__ uint32_t pkh2(float a, float b) {
    __half2 h = __floats2half2_rn(a, b);
    return *(uint32_t*)&h;
}
__device__ __forceinline__ void mma_f16(float c[4],
    uint32_t a0, uint32_t a1, uint32_t a2, uint32_t a3,
    uint32_t b0, uint32_t b1)
{
    asm volatile(
        "mma.sync.aligned.m16n8k16.row.col.f32.f16.f16.f32 "
        "{%0,%1,%2,%3}, {%4,%5,%6,%7}, {%8,%9}, {%0,%1,%2,%3};"
        : "+f"(c[0]), "+f"(c[1]), "+f"(c[2]), "+f"(c[3])
        : "r"(a0), "r"(a1), "r"(a2), "r"(a3), "r"(b0), "r"(b1));
}
__device__ __forceinline__ void ldsm_x4(uint32_t& r0, uint32_t& r1,
                                        uint32_t& r2, uint32_t& r3, uint32_t addr)
{
    asm volatile("ldmatrix.sync.aligned.m8n8.x4.shared.b16 {%0,%1,%2,%3}, [%4];"
                 : "=r"(r0), "=r"(r1), "=r"(r2), "=r"(r3) : "r"(addr));
}

// swizzled byte offset within a [rows][32]-half tile (64B rows, 4 x 16B chunks)
__device__ __forceinline__ uint32_t sw_off(int row, int kc) {
    return (uint32_t)(row * 64 + ((kc ^ ((row >> 1) & 3)) << 4));
}

// ---------------------------------------------------------------------------
// fp16 GEMM (fp32 accum): C[M,N] = A[M,256] @ W[256,N] + bias[N]
// Block 128x128, BK=32, 8 warps (4x2), warp tile 32x64, mma.m16n8k16.
// ldmatrix fragment loads from XOR-swizzled row-major smem; reg prefetch.
// ---------------------------------------------------------------------------
template<bool GATHER, bool AHALF, bool CHALF>
__global__ __launch_bounds__(256, 2) void gemm_f16_kernel(
    const void* __restrict__ Av, const float* __restrict__ W,
    const float* __restrict__ bias, void* __restrict__ Cv, int N)
{
    __shared__ __half Asm[128 * 32];   // [row][32] halves, swizzled chunks
    __shared__ __half Wsm[128 * 32];   // [n]  [32] halves (Bt: n-major, k contig)
    char* aB = (char*)Asm;
    char* wB = (char*)Wsm;

    const int t    = threadIdx.x;
    const int bm   = blockIdx.y, bn = blockIdx.x;
    const int lane = t & 31, warp = t >> 5;
    const int wm   = warp >> 1;      // 0..3 : 32-row strip
    const int wnn  = warp & 1;       // 0..1 : 64-col strip
    const int g    = lane >> 2;
    const int tq   = lane & 3;
    const int l15  = lane & 15, lhi = lane >> 4;

    // A stager: thread -> (row t>>1, k16-block t&1)
    const int arow = t >> 1, as_ = t & 1;
    size_t aoff;
    if (GATHER) {
        const int r    = bm * 128 + arow;
        const int wwin = r >> 6, p = r & 63;
        const int b    = wwin >> 8, widx = wwin & 255;
        const int wy   = widx >> 4, wx = widx & 15;
        const int py   = wy * 8 + (p >> 3);
        const int px   = wx * 8 + (p & 7);
        aoff = (((size_t)b * IMGH + py) * IMGW + px) * DIM;
    } else {
        aoff = (size_t)(bm * 128 + arow) * DIM;
    }
    const float*  ArowF = (const float*)Av + aoff;
    const __half* ArowH = (const __half*)Av + aoff;
    const uint32_t aSt0 = sw_off(arow, 2 * as_);
    const uint32_t aSt1 = sw_off(arow, 2 * as_ + 1);

    // W stager: thread -> (col n = t>>1, k16-block t&1)
    const int wn_ = t >> 1, kbw = t & 1;
    const float* Wcol = W + bn * 128 + wn_;
    const uint32_t wSt0 = sw_off(wn_, 2 * kbw);
    const uint32_t wSt1 = sw_off(wn_, 2 * kbw + 1);

    // ldmatrix lane addresses (shared-state-space u32)
    const uint32_t aBase = (uint32_t)__cvta_generic_to_shared(Asm);
    const uint32_t wBase = (uint32_t)__cvta_generic_to_shared(Wsm);
    // A: per mi, row = wm*32 + mi*16 + l15, kc = 2kb + lhi
    uint32_t aRow[2]; int aS[2];
    #pragma unroll
    for (int mi = 0; mi < 2; mi++) {
        int row = wm * 32 + mi * 16 + l15;
        aRow[mi] = aBase + row * 64;
        aS[mi]   = (row >> 1) & 3;
    }
    // B: per nt (0..3), row = wnn*64 + nt*16 + l15
    uint32_t bRow[4]; int bS[4];
    #pragma unroll
    for (int nt = 0; nt < 4; nt++) {
        int row = wnn * 64 + nt * 16 + l15;
        bRow[nt] = wBase + row * 64;
        bS[nt]   = (row >> 1) & 3;
    }

    float acc[2][8][4];
    #pragma unroll
    for (int mi = 0; mi < 2; mi++)
        #pragma unroll
        for (int ni = 0; ni < 8; ni++)
            #pragma unroll
            for (int j = 0; j < 4; j++) acc[mi][ni][j] = 0.f;

    uint32_t apk[8], wpk[8];

    // ---- initial prefetch ----
    if (AHALF) {
        const uint4* ap = (const uint4*)(ArowH + as_ * 16);
        uint4 u0 = ap[0], u1 = ap[1];
        apk[0]=u0.x; apk[1]=u0.y; apk[2]=u0.z; apk[3]=u0.w;
        apk[4]=u1.x; apk[5]=u1.y; apk[6]=u1.z; apk[7]=u1.w;
    } else {
        const float* ap = ArowF + as_ * 16;
        float4 v0 = *(const float4*)(ap);
        float4 v1 = *(const float4*)(ap + 4);
        float4 v2 = *(const float4*)(ap + 8);
        float4 v3 = *(const float4*)(ap + 12);
        apk[0]=pkh2(v0.x,v0.y); apk[1]=pkh2(v0.z,v0.w);
        apk[2]=pkh2(v1.x,v1.y); apk[3]=pkh2(v1.z,v1.w);
        apk[4]=pkh2(v2.x,v2.y); apk[5]=pkh2(v2.z,v2.w);
        apk[6]=pkh2(v3.x,v3.y); apk[7]=pkh2(v3.z,v3.w);
    }
    #pragma unroll
    for (int q = 0; q < 8; q++) {
        float w0 = Wcol[(size_t)(kbw * 16 + 2*q)     * N];
        float w1 = Wcol[(size_t)(kbw * 16 + 2*q + 1) * N];
        wpk[q] = pkh2(w0, w1);
    }

    for (int it = 0; it < 8; it++) {
        // ---- store staged regs to swizzled smem (2 x STS.128 each) ----
        *(uint4*)(aB + aSt0) = make_uint4(apk[0], apk[1], apk[2], apk[3]);
        *(uint4*)(aB + aSt1) = make_uint4(apk[4], apk[5], apk[6], apk[7]);
        *(uint4*)(wB + wSt0) = make_uint4(wpk[0], wpk[1], wpk[2], wpk[3]);
        *(uint4*)(wB + wSt1) = make_uint4(wpk[4], wpk[5], wpk[6], wpk[7]);
        __syncthreads();

        // ---- prefetch next iteration ----
        if (it < 7) {
            const int k0 = (it + 1) * 32;
            if (AHALF) {
                const uint4* ap = (const uint4*)(ArowH + k0 + as_ * 16);
                uint4 u0 = ap[0], u1 = ap[1];
                apk[0]=u0.x; apk[1]=u0.y; apk[2]=u0.z; apk[3]=u0.w;
                apk[4]=u1.x; apk[5]=u1.y; apk[6]=u1.z; apk[7]=u1.w;
            } else {
                const float* ap = ArowF + k0 + as_ * 16;
                float4 v0 = *(const float4*)(ap);
                float4 v1 = *(const float4*)(ap + 4);
                float4 v2 = *(const float4*)(ap + 8);
                float4 v3 = *(const float4*)(ap + 12);
                apk[0]=pkh2(v0.x,v0.y); apk[1]=pkh2(v0.z,v0.w);
                apk[2]=pkh2(v1.x,v1.y); apk[3]=pkh2(v1.z,v1.w);
                apk[4]=pkh2(v2.x,v2.y); apk[5]=pkh2(v2.z,v2.w);
                apk[6]=pkh2(v3.x,v3.y); apk[7]=pkh2(v3.z,v3.w);
            }
            #pragma unroll
            for (int q = 0; q < 8; q++) {
                float w0 = Wcol[(size_t)(k0 + kbw * 16 + 2*q)     * N];
                float w1 = Wcol[(size_t)(k0 + kbw * 16 + 2*q + 1) * N];
                wpk[q] = pkh2(w0, w1);
            }
        }

        // ---- compute 2 k16 blocks via ldmatrix ----
        #pragma unroll
        for (int kb = 0; kb < 2; kb++) {
            const int kc = 2 * kb + lhi;
            uint32_t a[2][4];
            #pragma unroll
            for (int mi = 0; mi < 2; mi++)
                ldsm_x4(a[mi][0], a[mi][1], a[mi][2], a[mi][3],
                        aRow[mi] + (uint32_t)(((kc ^ aS[mi]) << 4)));
            uint32_t b[4][4];
            #pragma unroll
            for (int nt = 0; nt < 4; nt++)
                ldsm_x4(b[nt][0], b[nt][1], b[nt][2], b[nt][3],
                        bRow[nt] + (uint32_t)(((kc ^ bS[nt]) << 4)));
            #pragma unroll
            for (int mi = 0; mi < 2; mi++)
                #pragma unroll
                for (int nt = 0; nt < 4; nt++) {
                    // tile order: r0 = (n0-7, k0-7), r1 = (n8-15, k0-7),
                    //             r2 = (n0-7, k8-15), r3 = (n8-15, k8-15)
                    mma_f16(acc[mi][2*nt],   a[mi][0], a[mi][1], a[mi][2], a[mi][3],
                            b[nt][0], b[nt][2]);
                    mma_f16(acc[mi][2*nt+1], a[mi][0], a[mi][1], a[mi][2], a[mi][3],
                            b[nt][1], b[nt][3]);
                }
        }
        __syncthreads();
    }

    // ---- epilogue ----
    #pragma unroll
    for (int mi = 0; mi < 2; mi++) {
        const int r0 = bm * 128 + wm * 32 + mi * 16 + g;
        #pragma unroll
        for (int ni = 0; ni < 8; ni++) {
            const int col = bn * 128 + wnn * 64 + ni * 8 + 2 * tq;
            float2 bv = *(const float2*)(bias + col);
            float c0 = acc[mi][ni][0] + bv.x, c1 = acc[mi][ni][1] + bv.y;
            float c2 = acc[mi][ni][2] + bv.x, c3 = acc[mi][ni][3] + bv.y;
            if (CHALF) {
                __half* C = (__half*)Cv;
                *(uint32_t*)(C + (size_t)r0 * N + col)       = pkh2(c0, c1);
                *(uint32_t*)(C + (size_t)(r0 + 8) * N + col) = pkh2(c2, c3);
            } else {
                float* C = (float*)Cv;
                *(float2*)(C + (size_t)r0 * N + col)       = make_float2(c0, c1);
                *(float2*)(C + (size_t)(r0 + 8) * N + col) = make_float2(c2, c3);
            }
        }
    }
}

// ---------------------------------------------------------------------------
// fp16 tensor-core attention with register-resident P (unchanged from R9).
// ---------------------------------------------------------------------------
__global__ __launch_bounds__(256) void attn_mma_kernel(const float* __restrict__ btab)
{
    __shared__ uint2  Qs2[256][12];
    __shared__ uint2  Kt2[64][12];
    __shared__ __half Vt_h[32][72];
    __shared__ __half Bs_h[64][66];

    const int blk = blockIdx.x;
    const int win = blk >> 3;
    const int h   = blk & 7;
    const int t   = threadIdx.x;
    const int lane = t & 31, warp = t >> 5;
    const int g   = lane >> 2;
    const int tq  = lane & 3;
    const int slot = (tq + ((g & 3) + 2 * (g >> 2))) & 3;

    {
        const __half* qp = g_q + ((size_t)(win * NQ + t)) * DIM + h * HD;
        const int rot = ((t & 3) + 2 * ((t >> 2) & 1)) & 3;
        const uint4* qp4 = (const uint4*)qp;
        uint4 u0 = qp4[0], u1 = qp4[1], u2 = qp4[2], u3 = qp4[3];
        uint32_t w[16] = {u0.x,u0.y,u0.z,u0.w, u1.x,u1.y,u1.z,u1.w,
                          u2.x,u2.y,u2.z,u2.w, u3.x,u3.y,u3.z,u3.w};
        #pragma unroll
        for (int q = 0; q < 4; q++) {
            Qs2[t][((q + rot) & 3)]     = make_uint2(w[q],     w[q + 4]);
            Qs2[t][4 + ((q + rot) & 3)] = make_uint2(w[8 + q], w[12 + q]);
        }
    }
    if (t < 64) {
        const __half* kp = g_kv + (size_t)(win * WS2 + t) * 512 + h * HD;
        const int rot = ((t & 3) + 2 * ((t >> 2) & 1)) & 3;
        const uint4* kp4 = (const uint4*)kp;
        uint4 u0 = kp4[0], u1 = kp4[1], u2 = kp4[2], u3 = kp4[3];
        uint32_t w[16] = {u0.x,u0.y,u0.z,u0.w, u1.x,u1.y,u1.z,u1.w,
                          u2.x,u2.y,u2.z,u2.w, u3.x,u3.y,u3.z,u3.w};
        #pragma unroll
        for (int q = 0; q < 4; q++) {
            Kt2[t][((q + rot) & 3)]     = make_uint2(w[q],     w[q + 4]);
            Kt2[t][4 + ((q + rot) & 3)] = make_uint2(w[8 + q], w[12 + q]);
        }
    } else if (t < 128) {
        const int key = t - 64;
        const __half2* vp2 = (const __half2*)(g_kv + (size_t)(win * WS2 + key) * 512
                                              + DIM + h * HD);
        #pragma unroll
        for (int j = 0; j < 16; j++) {
            __half2 v = vp2[j];
            Vt_h[2 * j][key]     = __low2half(v);
            Vt_h[2 * j + 1][key] = __high2half(v);
        }
    }
    #pragma unroll
    for (int i = 0; i < 16; i++) {
        int e  = t + i * 256;
        int qp = e >> 6, kp = e & 63;
        int dr = (qp >> 3) - (kp >> 3) + 7;
        int dc = (qp & 7)  - (kp & 7)  + 7;
        Bs_h[qp][kp] = __float2half(btab[(dr * 15 + dc) * HEADS + h]);
    }
    __syncthreads();

    float acc[2][8][4];
    #pragma unroll
    for (int mi = 0; mi < 2; mi++)
        #pragma unroll
        for (int ni = 0; ni < 8; ni++)
            #pragma unroll
            for (int j = 0; j < 4; j++) acc[mi][ni][j] = 0.f;

    #pragma unroll
    for (int kb = 0; kb < 2; kb++) {
        const int c = kb * 4 + slot;
        uint2 lo[2], hi[2];
        #pragma unroll
        for (int mi = 0; mi < 2; mi++) {
            const int r0 = warp * 32 + mi * 16 + g;
            lo[mi] = Qs2[r0][c];
            hi[mi] = Qs2[r0 + 8][c];
        }
        uint2 bf[8];
        #pragma unroll
        for (int ni = 0; ni < 8; ni++)
            bf[ni] = Kt2[ni * 8 + g][c];
        #pragma unroll
        for (int mi = 0; mi < 2; mi++)
            #pragma unroll
            for (int ni = 0; ni < 8; ni++)
                mma_f16(acc[mi][ni], lo[mi].x, hi[mi].x, lo[mi].y, hi[mi].y,
                        bf[ni].x, bf[ni].y);
    }

    const float scale = 0.17677669529663687f;
    float inv_[2][2];
    #pragma unroll
    for (int mi = 0; mi < 2; mi++) {
        const int rA = warp * 32 + mi * 16 + g;
        const int qA = rA & 63, qB = (rA + 8) & 63;
        float mA = -1e30f, mB = -1e30f;
        #pragma unroll
        for (int ni = 0; ni < 8; ni++) {
            const int col = ni * 8 + 2 * tq;
            float2 bA = __half22float2(*(const __half2*)&Bs_h[qA][col]);
            float2 bB = __half22float2(*(const __half2*)&Bs_h[qB][col]);
            acc[mi][ni][0] = acc[mi][ni][0] * scale + bA.x;
            acc[mi][ni][1] = acc[mi][ni][1] * scale + bA.y;
            acc[mi][ni][2] = acc[mi][ni][2] * scale + bB.x;
            acc[mi][ni][3] = acc[mi][ni][3] * scale + bB.y;
            mA = fmaxf(mA, fmaxf(acc[mi][ni][0], acc[mi][ni][1]));
            mB = fmaxf(mB, fmaxf(acc[mi][ni][2], acc[mi][ni][3]));
        }
        mA = fmaxf(mA, __shfl_xor_sync(0xffffffff, mA, 1));
        mA = fmaxf(mA, __shfl_xor_sync(0xffffffff, mA, 2));
        mB = fmaxf(mB, __shfl_xor_sync(0xffffffff, mB, 1));
        mB = fmaxf(mB, __shfl_xor_sync(0xffffffff, mB, 2));
        float sA = 0.f, sB = 0.f;
        #pragma unroll
        for (int ni = 0; ni < 8; ni++) {
            float e0 = __expf(acc[mi][ni][0] - mA);
            float e1 = __expf(acc[mi][ni][1] - mA);
            float e2 = __expf(acc[mi][ni][2] - mB);
            float e3 = __expf(acc[mi][ni][3] - mB);
            acc[mi][ni][0] = e0; acc[mi][ni][1] = e1;
            acc[mi][ni][2] = e2; acc[mi][ni][3] = e3;
            sA += e0 + e1; sB += e2 + e3;
        }
        sA += __shfl_xor_sync(0xffffffff, sA, 1);
        sA += __shfl_xor_sync(0xffffffff, sA, 2);
        sB += __shfl_xor_sync(0xffffffff, sB, 1);
        sB += __shfl_xor_sync(0xffffffff, sB, 2);
        inv_[mi][0] = 1.f / sA;
        inv_[mi][1] = 1.f / sB;
    }

    float o[2][4][4];
    #pragma unroll
    for (int mi = 0; mi < 2; mi++)
        #pragma unroll
        for (int ni = 0; ni < 4; ni++)
            #pragma unroll
            for (int j = 0; j < 4; j++) o[mi][ni][j] = 0.f;

    #pragma unroll
    for (int kb = 0; kb < 4; kb++) {
        uint32_t a0[2], a1[2], a2[2], a3[2];
        #pragma unroll
        for (int mi = 0; mi < 2; mi++) {
            a0[mi] = pkh2(acc[mi][2*kb][0],     acc[mi][2*kb][1]);
            a1[mi] = pkh2(acc[mi][2*kb][2],     acc[mi][2*kb][3]);
            a2[mi] = pkh2(acc[mi][2*kb+1][0],   acc[mi][2*kb+1][1]);
            a3[mi] = pkh2(acc[mi][2*kb+1][2],   acc[mi][2*kb+1][3]);
        }
        #pragma unroll
        for (int ni = 0; ni < 4; ni++) {
            const __half* vrow = &Vt_h[ni * 8 + g][0];
            uint32_t b0 = *(const uint32_t*)(vrow + 16 * kb + 2 * tq);
            uint32_t b1 = *(const uint32_t*)(vrow + 16 * kb + 8 + 2 * tq);
            #pragma unroll
            for (int mi = 0; mi < 2; mi++)
                mma_f16(o[mi][ni], a0[mi], a1[mi], a2[mi], a3[mi], b0, b1);
        }
    }

    #pragma unroll
    for (int mi = 0; mi < 2; mi++) {
        const int r = win * NQ + warp * 32 + mi * 16 + g;
        const float ivA = inv_[mi][0], ivB = inv_[mi][1];
        #pragma unroll
        for (int ni = 0; ni < 4; ni++) {
            const int col = h * HD + ni * 8 + 2 * tq;
            *(uint32_t*)(g_att + (size_t)r * DIM + col) =
                pkh2(o[mi][ni][0] * ivA, o[mi][ni][1] * ivA);
            *(uint32_t*)(g_att + (size_t)(r + 8) * DIM + col) =
                pkh2(o[mi][ni][2] * ivB, o[mi][ni][3] * ivB);
        }
    }
}

// ---------------------------------------------------------------------------
extern "C" void kernel_launch(void* const* d_in, const int* in_sizes, int n_in,
                              void* d_out, int out_size)
{
    const float* gauss = (const float*)d_in[0];
    const float* img   = (const float*)d_in[1];
    const float* btab  = (const float*)d_in[2];
    const float* Wq    = (const float*)d_in[3];
    const float* bq    = (const float*)d_in[4];
    const float* Wkv   = (const float*)d_in[5];
    const float* bkv   = (const float*)d_in[6];
    const float* Wp    = (const float*)d_in[7];
    const float* bp    = (const float*)d_in[8];
    float* out = (float*)d_out;

    void* pq = nullptr;   cudaGetSymbolAddress(&pq, g_q);
    void* pkv = nullptr;  cudaGetSymbolAddress(&pkv, g_kv);
    void* pa = nullptr;   cudaGetSymbolAddress(&pa, g_att);

    // 1) Q projection: fp32 A -> fp16 C
    gemm_f16_kernel<false, false, true>
        <<<dim3(DIM / 128, ROWS_Q / 128), 256>>>(gauss, Wq, bq, pq, DIM);
    // 2) KV projection (window gather): fp32 A -> fp16 C
    gemm_f16_kernel<true, false, true>
        <<<dim3((2 * DIM) / 128, ROWS_KV / 128), 256>>>(img, Wkv, bkv, pkv, 2 * DIM);
    // 3) Attention (fp16 MMA, register-resident P)
    attn_mma_kernel<<<BW * HEADS, 256>>>(btab);
    // 4) Output projection: fp16 A -> fp32 C (d_out)
    gemm_f16_kernel<false, true, false>
        <<<dim3(DIM / 128, ROWS_Q / 128), 256>>>(pa, Wp, bp, out, DIM);
}

// round 12
// speedup vs baseline: 2.7465x; 1.0671x over previous
#include <cuda_runtime.h>
#include <cuda_fp16.h>
#include <cstdint>

#define WS    8
#define MQ    4
#define HEADS 8
#define DIM   256
#define HD    32
#define BATCH 4
#define IMGH  128
#define IMGW  128
#define NWIN  256
#define BW    (BATCH*NWIN)   // 1024 windows
#define WS2   64
#define NQ    (MQ*WS2)       // 256
#define ROWS_Q  (BW*NQ)      // 262144
#define ROWS_KV (BW*WS2)     // 65536

__device__ __half g_q   [ROWS_Q  * DIM];
__device__ __half g_kv  [ROWS_KV * 2 * DIM];
__device__ __half g_att [ROWS_Q  * DIM];
__device__ __half g_bias[HEADS * WS2 * WS2];   // [h][q][k] fp16, 64KB

__device__ __forceinline__ uint32_t pkh2(float a, float b) {
    __half2 h = __floats2half2_rn(a, b);
    return *(uint32_t*)&h;
}
__device__ __forceinline__ void mma_f16(float c[4],
    uint32_t a0, uint32_t a1, uint32_t a2, uint32_t a3,
    uint32_t b0, uint32_t b1)
{
    asm volatile(
        "mma.sync.aligned.m16n8k16.row.col.f32.f16.f16.f32 "
        "{%0,%1,%2,%3}, {%4,%5,%6,%7}, {%8,%9}, {%0,%1,%2,%3};"
        : "+f"(c[0]), "+f"(c[1]), "+f"(c[2]), "+f"(c[3])
        : "r"(a0), "r"(a1), "r"(a2), "r"(a3), "r"(b0), "r"(b1));
}
__device__ __forceinline__ void ldsm_x4(uint32_t& r0, uint32_t& r1,
                                        uint32_t& r2, uint32_t& r3, uint32_t addr)
{
    asm volatile("ldmatrix.sync.aligned.m8n8.x4.shared.b16 {%0,%1,%2,%3}, [%4];"
                 : "=r"(r0), "=r"(r1), "=r"(r2), "=r"(r3) : "r"(addr));
}

// swizzled byte offset within a [rows][32]-half tile (64B rows, 4 x 16B chunks)
__device__ __forceinline__ uint32_t sw_off(int row, int kc) {
    return (uint32_t)(row * 64 + ((kc ^ ((row >> 1) & 3)) << 4));
}

// ---------------------------------------------------------------------------
// bias precompute: g_bias[h][q][k] = btab[rel(q,k)][h]  (8 blocks x 256 thr)
// ---------------------------------------------------------------------------
__global__ void bias_prep_kernel(const float* __restrict__ btab)
{
    const int h = blockIdx.x;
    const int t = threadIdx.x;
    #pragma unroll
    for (int i = 0; i < 16; i++) {
        int e  = t + i * 256;            // 0..4095
        int qp = e >> 6, kp = e & 63;
        int dr = (qp >> 3) - (kp >> 3) + 7;
        int dc = (qp & 7)  - (kp & 7)  + 7;
        g_bias[h * 4096 + e] = __float2half(btab[(dr * 15 + dc) * HEADS + h]);
    }
}

// ---------------------------------------------------------------------------
// fp16 GEMM (fp32 accum): C[M,N] = A[M,256] @ W[256,N] + bias[N]
// Block 128x128, BK=32, 8 warps (4x2), warp tile 32x64, mma.m16n8k16.
// Double-buffered swizzled smem (ONE syncthreads per iter), ldmatrix loads.
// ---------------------------------------------------------------------------
template<bool GATHER, bool AHALF, bool CHALF>
__global__ __launch_bounds__(256, 2) void gemm_f16_kernel(
    const void* __restrict__ Av, const float* __restrict__ W,
    const float* __restrict__ bias, void* __restrict__ Cv, int N)
{
    __shared__ __half Asm[2][128 * 32];
    __shared__ __half Wsm[2][128 * 32];

    const int t    = threadIdx.x;
    const int bm   = blockIdx.y, bn = blockIdx.x;
    const int lane = t & 31, warp = t >> 5;
    const int wm   = warp >> 1;
    const int wnn  = warp & 1;
    const int g    = lane >> 2;
    const int tq   = lane & 3;
    const int l15  = lane & 15, lhi = lane >> 4;

    // A stager: thread -> (row t>>1, k16-block t&1)
    const int arow = t >> 1, as_ = t & 1;
    size_t aoff;
    if (GATHER) {
        const int r    = bm * 128 + arow;
        const int wwin = r >> 6, p = r & 63;
        const int b    = wwin >> 8, widx = wwin & 255;
        const int wy   = widx >> 4, wx = widx & 15;
        const int py   = wy * 8 + (p >> 3);
        const int px   = wx * 8 + (p & 7);
        aoff = (((size_t)b * IMGH + py) * IMGW + px) * DIM;
    } else {
        aoff = (size_t)(bm * 128 + arow) * DIM;
    }
    const float*  ArowF = (const float*)Av + aoff;
    const __half* ArowH = (const __half*)Av + aoff;
    const uint32_t aSt0 = sw_off(arow, 2 * as_);
    const uint32_t aSt1 = sw_off(arow, 2 * as_ + 1);

    // W stager: thread -> (col n = t>>1, k16-block t&1)
    const int wn_ = t >> 1, kbw = t & 1;
    const float* Wcol = W + bn * 128 + wn_;
    const uint32_t wSt0 = sw_off(wn_, 2 * kbw);
    const uint32_t wSt1 = sw_off(wn_, 2 * kbw + 1);

    const uint32_t aBase = (uint32_t)__cvta_generic_to_shared(Asm);
    const uint32_t wBase = (uint32_t)__cvta_generic_to_shared(Wsm);
    uint32_t aRow[2]; int aS[2];
    #pragma unroll
    for (int mi = 0; mi < 2; mi++) {
        int row = wm * 32 + mi * 16 + l15;
        aRow[mi] = aBase + row * 64;
        aS[mi]   = (row >> 1) & 3;
    }
    uint32_t bRow[4]; int bS[4];
    #pragma unroll
    for (int nt = 0; nt < 4; nt++) {
        int row = wnn * 64 + nt * 16 + l15;
        bRow[nt] = wBase + row * 64;
        bS[nt]   = (row >> 1) & 3;
    }

    float acc[2][8][4];
    #pragma unroll
    for (int mi = 0; mi < 2; mi++)
        #pragma unroll
        for (int ni = 0; ni < 8; ni++)
            #pragma unroll
            for (int j = 0; j < 4; j++) acc[mi][ni][j] = 0.f;

    uint32_t apk[8], wpk[8];

    // ---- prologue: load iter 0 and store to buffer 0 ----
    {
        if (AHALF) {
            const uint4* ap = (const uint4*)(ArowH + as_ * 16);
            uint4 u0 = ap[0], u1 = ap[1];
            apk[0]=u0.x; apk[1]=u0.y; apk[2]=u0.z; apk[3]=u0.w;
            apk[4]=u1.x; apk[5]=u1.y; apk[6]=u1.z; apk[7]=u1.w;
        } else {
            const float* ap = ArowF + as_ * 16;
            float4 v0 = *(const float4*)(ap);
            float4 v1 = *(const float4*)(ap + 4);
            float4 v2 = *(const float4*)(ap + 8);
            float4 v3 = *(const float4*)(ap + 12);
            apk[0]=pkh2(v0.x,v0.y); apk[1]=pkh2(v0.z,v0.w);
            apk[2]=pkh2(v1.x,v1.y); apk[3]=pkh2(v1.z,v1.w);
            apk[4]=pkh2(v2.x,v2.y); apk[5]=pkh2(v2.z,v2.w);
            apk[6]=pkh2(v3.x,v3.y); apk[7]=pkh2(v3.z,v3.w);
        }
        #pragma unroll
        for (int q = 0; q < 8; q++) {
            float w0 = Wcol[(size_t)(kbw * 16 + 2*q)     * N];
            float w1 = Wcol[(size_t)(kbw * 16 + 2*q + 1) * N];
            wpk[q] = pkh2(w0, w1);
        }
        char* aT = (char*)Asm[0];
        char* wT = (char*)Wsm[0];
        *(uint4*)(aT + aSt0) = make_uint4(apk[0], apk[1], apk[2], apk[3]);
        *(uint4*)(aT + aSt1) = make_uint4(apk[4], apk[5], apk[6], apk[7]);
        *(uint4*)(wT + wSt0) = make_uint4(wpk[0], wpk[1], wpk[2], wpk[3]);
        *(uint4*)(wT + wSt1) = make_uint4(wpk[4], wpk[5], wpk[6], wpk[7]);
    }
    __syncthreads();

    for (int it = 0; it < 8; it++) {
        const uint32_t bufOff = (uint32_t)(it & 1) * 8192;

        // ---- issue next iteration's global loads ----
        if (it < 7) {
            const int k0 = (it + 1) * 32;
            if (AHALF) {
                const uint4* ap = (const uint4*)(ArowH + k0 + as_ * 16);
                uint4 u0 = ap[0], u1 = ap[1];
                apk[0]=u0.x; apk[1]=u0.y; apk[2]=u0.z; apk[3]=u0.w;
                apk[4]=u1.x; apk[5]=u1.y; apk[6]=u1.z; apk[7]=u1.w;
            } else {
                const float* ap = ArowF + k0 + as_ * 16;
                float4 v0 = *(const float4*)(ap);
                float4 v1 = *(const float4*)(ap + 4);
                float4 v2 = *(const float4*)(ap + 8);
                float4 v3 = *(const float4*)(ap + 12);
                apk[0]=pkh2(v0.x,v0.y); apk[1]=pkh2(v0.z,v0.w);
                apk[2]=pkh2(v1.x,v1.y); apk[3]=pkh2(v1.z,v1.w);
                apk[4]=pkh2(v2.x,v2.y); apk[5]=pkh2(v2.z,v2.w);
                apk[6]=pkh2(v3.x,v3.y); apk[7]=pkh2(v3.z,v3.w);
            }
            #pragma unroll
            for (int q = 0; q < 8; q++) {
                float w0 = Wcol[(size_t)(k0 + kbw * 16 + 2*q)     * N];
                float w1 = Wcol[(size_t)(k0 + kbw * 16 + 2*q + 1) * N];
                wpk[q] = pkh2(w0, w1);
            }
        }

        // ---- compute 2 k16 blocks from current buffer ----
        #pragma unroll
        for (int kb = 0; kb < 2; kb++) {
            const int kc = 2 * kb + lhi;
            uint32_t a[2][4];
            #pragma unroll
            for (int mi = 0; mi < 2; mi++)
                ldsm_x4(a[mi][0], a[mi][1], a[mi][2], a[mi][3],
                        aRow[mi] + bufOff + (uint32_t)(((kc ^ aS[mi]) << 4)));
            uint32_t b[4][4];
            #pragma unroll
            for (int nt = 0; nt < 4; nt++)
                ldsm_x4(b[nt][0], b[nt][1], b[nt][2], b[nt][3],
                        bRow[nt] + bufOff + (uint32_t)(((kc ^ bS[nt]) << 4)));
            #pragma unroll
            for (int mi = 0; mi < 2; mi++)
                #pragma unroll
                for (int nt = 0; nt < 4; nt++) {
                    mma_f16(acc[mi][2*nt],   a[mi][0], a[mi][1], a[mi][2], a[mi][3],
                            b[nt][0], b[nt][2]);
                    mma_f16(acc[mi][2*nt+1], a[mi][0], a[mi][1], a[mi][2], a[mi][3],
                            b[nt][1], b[nt][3]);
                }
        }

        // ---- store next iteration into the other buffer ----
        if (it < 7) {
            char* aT = (char*)Asm[(it + 1) & 1];
            char* wT = (char*)Wsm[(it + 1) & 1];
            *(uint4*)(aT + aSt0) = make_uint4(apk[0], apk[1], apk[2], apk[3]);
            *(uint4*)(aT + aSt1) = make_uint4(apk[4], apk[5], apk[6], apk[7]);
            *(uint4*)(wT + wSt0) = make_uint4(wpk[0], wpk[1], wpk[2], wpk[3]);
            *(uint4*)(wT + wSt1) = make_uint4(wpk[4], wpk[5], wpk[6], wpk[7]);
        }
        __syncthreads();
    }

    // ---- epilogue ----
    #pragma unroll
    for (int mi = 0; mi < 2; mi++) {
        const int r0 = bm * 128 + wm * 32 + mi * 16 + g;
        #pragma unroll
        for (int ni = 0; ni < 8; ni++) {
            const int col = bn * 128 + wnn * 64 + ni * 8 + 2 * tq;
            float2 bv = *(const float2*)(bias + col);
            float c0 = acc[mi][ni][0] + bv.x, c1 = acc[mi][ni][1] + bv.y;
            float c2 = acc[mi][ni][2] + bv.x, c3 = acc[mi][ni][3] + bv.y;
            if (CHALF) {
                __half* C = (__half*)Cv;
                *(uint32_t*)(C + (size_t)r0 * N + col)       = pkh2(c0, c1);
                *(uint32_t*)(C + (size_t)(r0 + 8) * N + col) = pkh2(c2, c3);
            } else {
                float* C = (float*)Cv;
                *(float2*)(C + (size_t)r0 * N + col)       = make_float2(c0, c1);
                *(float2*)(C + (size_t)(r0 + 8) * N + col) = make_float2(c2, c3);
            }
        }
    }
}

// ---------------------------------------------------------------------------
// fp16 tensor-core attention, register-resident P; bias from precomputed
// g_bias via coalesced uint4 loads (replaces the 4B gather).
// ---------------------------------------------------------------------------
__global__ __launch_bounds__(256) void attn_mma_kernel()
{
    __shared__ uint2  Qs2[256][12];
    __shared__ uint2  Kt2[64][12];
    __shared__ __half Vt_h[32][72];
    __shared__ __half Bs_h[64][66];

    const int blk = blockIdx.x;
    const int win = blk >> 3;
    const int h   = blk & 7;
    const int t   = threadIdx.x;
    const int lane = t & 31, warp = t >> 5;
    const int g   = lane >> 2;
    const int tq  = lane & 3;
    const int slot = (tq + ((g & 3) + 2 * (g >> 2))) & 3;

    {
        const __half* qp = g_q + ((size_t)(win * NQ + t)) * DIM + h * HD;
        const int rot = ((t & 3) + 2 * ((t >> 2) & 1)) & 3;
        const uint4* qp4 = (const uint4*)qp;
        uint4 u0 = qp4[0], u1 = qp4[1], u2 = qp4[2], u3 = qp4[3];
        uint32_t w[16] = {u0.x,u0.y,u0.z,u0.w, u1.x,u1.y,u1.z,u1.w,
                          u2.x,u2.y,u2.z,u2.w, u3.x,u3.y,u3.z,u3.w};
        #pragma unroll
        for (int q = 0; q < 4; q++) {
            Qs2[t][((q + rot) & 3)]     = make_uint2(w[q],     w[q + 4]);
            Qs2[t][4 + ((q + rot) & 3)] = make_uint2(w[8 + q], w[12 + q]);
        }
    }
    if (t < 64) {
        const __half* kp = g_kv + (size_t)(win * WS2 + t) * 512 + h * HD;
        const int rot = ((t & 3) + 2 * ((t >> 2) & 1)) & 3;
        const uint4* kp4 = (const uint4*)kp;
        uint4 u0 = kp4[0], u1 = kp4[1], u2 = kp4[2], u3 = kp4[3];
        uint32_t w[16] = {u0.x,u0.y,u0.z,u0.w, u1.x,u1.y,u1.z,u1.w,
                          u2.x,u2.y,u2.z,u2.w, u3.x,u3.y,u3.z,u3.w};
        #pragma unroll
        for (int q = 0; q < 4; q++) {
            Kt2[t][((q + rot) & 3)]     = make_uint2(w[q],     w[q + 4]);
            Kt2[t][4 + ((q + rot) & 3)] = make_uint2(w[8 + q], w[12 + q]);
        }
    } else if (t < 128) {
        const int key = t - 64;
        const __half2* vp2 = (const __half2*)(g_kv + (size_t)(win * WS2 + key) * 512
                                              + DIM + h * HD);
        #pragma unroll
        for (int j = 0; j < 16; j++) {
            __half2 v = vp2[j];
            Vt_h[2 * j][key]     = __low2half(v);
            Vt_h[2 * j + 1][key] = __high2half(v);
        }
    }
    // ---- stage bias: coalesced from precomputed per-head table ----
    {
        const __half* gb = g_bias + h * 4096;
        #pragma unroll
        for (int i = 0; i < 2; i++) {
            int idx = t + i * 256;            // 0..511 groups of 8 halves
            int qp = idx >> 3, c8 = (idx & 7) * 8;
            uint4 u = *(const uint4*)(gb + qp * 64 + c8);
            uint32_t* dst = (uint32_t*)((char*)&Bs_h[qp][0] + c8 * 2);
            dst[0] = u.x; dst[1] = u.y; dst[2] = u.z; dst[3] = u.w;
        }
    }
    __syncthreads();

    float acc[2][8][4];
    #pragma unroll
    for (int mi = 0; mi < 2; mi++)
        #pragma unroll
        for (int ni = 0; ni < 8; ni++)
            #pragma unroll
            for (int j = 0; j < 4; j++) acc[mi][ni][j] = 0.f;

    #pragma unroll
    for (int kb = 0; kb < 2; kb++) {
        const int c = kb * 4 + slot;
        uint2 lo[2], hi[2];
        #pragma unroll
        for (int mi = 0; mi < 2; mi++) {
            const int r0 = warp * 32 + mi * 16 + g;
            lo[mi] = Qs2[r0][c];
            hi[mi] = Qs2[r0 + 8][c];
        }
        uint2 bf[8];
        #pragma unroll
        for (int ni = 0; ni < 8; ni++)
            bf[ni] = Kt2[ni * 8 + g][c];
        #pragma unroll
        for (int mi = 0; mi < 2; mi++)
            #pragma unroll
            for (int ni = 0; ni < 8; ni++)
                mma_f16(acc[mi][ni], lo[mi].x, hi[mi].x, lo[mi].y, hi[mi].y,
                        bf[ni].x, bf[ni].y);
    }

    const float scale = 0.17677669529663687f;
    float inv_[2][2];
    #pragma unroll
    for (int mi = 0; mi < 2; mi++) {
        const int rA = warp * 32 + mi * 16 + g;
        const int qA = rA & 63, qB = (rA + 8) & 63;
        float mA = -1e30f, mB = -1e30f;
        #pragma unroll
        for (int ni = 0; ni < 8; ni++) {
            const int col = ni * 8 + 2 * tq;
            float2 bA = __half22float2(*(const __half2*)&Bs_h[qA][col]);
            float2 bB = __half22float2(*(const __half2*)&Bs_h[qB][col]);
            acc[mi][ni][0] = acc[mi][ni][0] * scale + bA.x;
            acc[mi][ni][1] = acc[mi][ni][1] * scale + bA.y;
            acc[mi][ni][2] = acc[mi][ni][2] * scale + bB.x;
            acc[mi][ni][3] = acc[mi][ni][3] * scale + bB.y;
            mA = fmaxf(mA, fmaxf(acc[mi][ni][0], acc[mi][ni][1]));
            mB = fmaxf(mB, fmaxf(acc[mi][ni][2], acc[mi][ni][3]));
        }
        mA = fmaxf(mA, __shfl_xor_sync(0xffffffff, mA, 1));
        mA = fmaxf(mA, __shfl_xor_sync(0xffffffff, mA, 2));
        mB = fmaxf(mB, __shfl_xor_sync(0xffffffff, mB, 1));
        mB = fmaxf(mB, __shfl_xor_sync(0xffffffff, mB, 2));
        float sA = 0.f, sB = 0.f;
        #pragma unroll
        for (int ni = 0; ni < 8; ni++) {
            float e0 = __expf(acc[mi][ni][0] - mA);
            float e1 = __expf(acc[mi][ni][1] - mA);
            float e2 = __expf(acc[mi][ni][2] - mB);
            float e3 = __expf(acc[mi][ni][3] - mB);
            acc[mi][ni][0] = e0; acc[mi][ni][1] = e1;
            acc[mi][ni][2] = e2; acc[mi][ni][3] = e3;
            sA += e0 + e1; sB += e2 + e3;
        }
        sA += __shfl_xor_sync(0xffffffff, sA, 1);
        sA += __shfl_xor_sync(0xffffffff, sA, 2);
        sB += __shfl_xor_sync(0xffffffff, sB, 1);
        sB += __shfl_xor_sync(0xffffffff, sB, 2);
        inv_[mi][0] = 1.f / sA;
        inv_[mi][1] = 1.f / sB;
    }

    float o[2][4][4];
    #pragma unroll
    for (int mi = 0; mi < 2; mi++)
        #pragma unroll
        for (int ni = 0; ni < 4; ni++)
            #pragma unroll
            for (int j = 0; j < 4; j++) o[mi][ni][j] = 0.f;

    #pragma unroll
    for (int kb = 0; kb < 4; kb++) {
        uint32_t a0[2], a1[2], a2[2], a3[2];
        #pragma unroll
        for (int mi = 0; mi < 2; mi++) {
            a0[mi] = pkh2(acc[mi][2*kb][0],     acc[mi][2*kb][1]);
            a1[mi] = pkh2(acc[mi][2*kb][2],     acc[mi][2*kb][3]);
            a2[mi] = pkh2(acc[mi][2*kb+1][0],   acc[mi][2*kb+1][1]);
            a3[mi] = pkh2(acc[mi][2*kb+1][2],   acc[mi][2*kb+1][3]);
        }
        #pragma unroll
        for (int ni = 0; ni < 4; ni++) {
            const __half* vrow = &Vt_h[ni * 8 + g][0];
            uint32_t b0 = *(const uint32_t*)(vrow + 16 * kb + 2 * tq);
            uint32_t b1 = *(const uint32_t*)(vrow + 16 * kb + 8 + 2 * tq);
            #pragma unroll
            for (int mi = 0; mi < 2; mi++)
                mma_f16(o[mi][ni], a0[mi], a1[mi], a2[mi], a3[mi], b0, b1);
        }
    }

    #pragma unroll
    for (int mi = 0; mi < 2; mi++) {
        const int r = win * NQ + warp * 32 + mi * 16 + g;
        const float ivA = inv_[mi][0], ivB = inv_[mi][1];
        #pragma unroll
        for (int ni = 0; ni < 4; ni++) {
            const int col = h * HD + ni * 8 + 2 * tq;
            *(uint32_t*)(g_att + (size_t)r * DIM + col) =
                pkh2(o[mi][ni][0] * ivA, o[mi][ni][1] * ivA);
            *(uint32_t*)(g_att + (size_t)(r + 8) * DIM + col) =
                pkh2(o[mi][ni][2] * ivB, o[mi][ni][3] * ivB);
        }
    }
}

// ---------------------------------------------------------------------------
extern "C" void kernel_launch(void* const* d_in, const int* in_sizes, int n_in,
                              void* d_out, int out_size)
{
    const float* gauss = (const float*)d_in[0];
    const float* img   = (const float*)d_in[1];
    const float* btab  = (const float*)d_in[2];
    const float* Wq    = (const float*)d_in[3];
    const float* bq    = (const float*)d_in[4];
    const float* Wkv   = (const float*)d_in[5];
    const float* bkv   = (const float*)d_in[6];
    const float* Wp    = (const float*)d_in[7];
    const float* bp    = (const float*)d_in[8];
    float* out = (float*)d_out;

    void* pq = nullptr;   cudaGetSymbolAddress(&pq, g_q);
    void* pkv = nullptr;  cudaGetSymbolAddress(&pkv, g_kv);
    void* pa = nullptr;   cudaGetSymbolAddress(&pa, g_att);

    // 0) bias table precompute (tiny)
    bias_prep_kernel<<<HEADS, 256>>>(btab);
    // 1) Q projection: fp32 A -> fp16 C
    gemm_f16_kernel<false, false, true>
        <<<dim3(DIM / 128, ROWS_Q / 128), 256>>>(gauss, Wq, bq, pq, DIM);
    // 2) KV projection (window gather): fp32 A -> fp16 C
    gemm_f16_kernel<true, false, true>
        <<<dim3((2 * DIM) / 128, ROWS_KV / 128), 256>>>(img, Wkv, bkv, pkv, 2 * DIM);
    // 3) Attention (fp16 MMA, register-resident P, precomputed bias)
    attn_mma_kernel<<<BW * HEADS, 256>>>();
    // 4) Output projection: fp16 A -> fp32 C (d_out)
    gemm_f16_kernel<false, true, false>
        <<<dim3(DIM / 128, ROWS_Q / 128), 256>>>(pa, Wp, bp, out, DIM);
}

// round 13
// speedup vs baseline: 2.9317x; 1.0674x over previous
#include <cuda_runtime.h>
#include <cuda_fp16.h>
#include <cstdint>

#define WS    8
#define MQ    4
#define HEADS 8
#define DIM   256
#define HD    32
#define BATCH 4
#define IMGH  128
#define IMGW  128
#define NWIN  256
#define BW    (BATCH*NWIN)   // 1024 windows
#define WS2   64
#define NQ    (MQ*WS2)       // 256
#define ROWS_Q  (BW*NQ)      // 262144
#define ROWS_KV (BW*WS2)     // 65536

__device__ __half g_q   [ROWS_Q  * DIM];
__device__ __half g_kv  [ROWS_KV * 2 * DIM];
__device__ __half g_att [ROWS_Q  * DIM];
__device__ __half g_bias[HEADS * WS2 * WS2];     // [h][q][k] fp16
// transposed fp16 weights, [n][k] with k contiguous (256 halves per row):
//   wq: rows [0,256)   wkv: rows [256,768)   wp: rows [768,1024)
__device__ __half g_wt  [1024 * DIM];

__device__ __forceinline__ uint32_t pkh2(float a, float b) {
    __half2 h = __floats2half2_rn(a, b);
    return *(uint32_t*)&h;
}
__device__ __forceinline__ void mma_f16(float c[4],
    uint32_t a0, uint32_t a1, uint32_t a2, uint32_t a3,
    uint32_t b0, uint32_t b1)
{
    asm volatile(
        "mma.sync.aligned.m16n8k16.row.col.f32.f16.f16.f32 "
        "{%0,%1,%2,%3}, {%4,%5,%6,%7}, {%8,%9}, {%0,%1,%2,%3};"
        : "+f"(c[0]), "+f"(c[1]), "+f"(c[2]), "+f"(c[3])
        : "r"(a0), "r"(a1), "r"(a2), "r"(a3), "r"(b0), "r"(b1));
}
__device__ __forceinline__ void ldsm_x4(uint32_t& r0, uint32_t& r1,
                                        uint32_t& r2, uint32_t& r3, uint32_t addr)
{
    asm volatile("ldmatrix.sync.aligned.m8n8.x4.shared.b16 {%0,%1,%2,%3}, [%4];"
                 : "=r"(r0), "=r"(r1), "=r"(r2), "=r"(r3) : "r"(addr));
}

// swizzled byte offset within a [rows][32]-half tile (64B rows, 4 x 16B chunks)
__device__ __forceinline__ uint32_t sw_off(int row, int kc) {
    return (uint32_t)(row * 64 + ((kc ^ ((row >> 1) & 3)) << 4));
}

// ---------------------------------------------------------------------------
// prep: bias table + transposed fp16 weights (both tiny)
// ---------------------------------------------------------------------------
__global__ void bias_prep_kernel(const float* __restrict__ btab)
{
    const int h = blockIdx.x;
    const int t = threadIdx.x;
    #pragma unroll
    for (int i = 0; i < 16; i++) {
        int e  = t + i * 256;
        int qp = e >> 6, kp = e & 63;
        int dr = (qp >> 3) - (kp >> 3) + 7;
        int dc = (qp & 7)  - (kp & 7)  + 7;
        g_bias[h * 4096 + e] = __float2half(btab[(dr * 15 + dc) * HEADS + h]);
    }
}
__global__ void w_prep_kernel(const float* __restrict__ Wq,
                              const float* __restrict__ Wkv,
                              const float* __restrict__ Wp)
{
    const int idx = blockIdx.x * 256 + threadIdx.x;   // 0 .. 262143
    const int row = idx >> 8;                         // n-row in g_wt
    const int k   = idx & 255;
    float v;
    if (row < 256)       v = Wq [(size_t)k * 256 + row];
    else if (row < 768)  v = Wkv[(size_t)k * 512 + (row - 256)];
    else                 v = Wp [(size_t)k * 256 + (row - 768)];
    g_wt[idx] = __float2half(v);
}

// ---------------------------------------------------------------------------
// fp16 GEMM (fp32 accum): C[M,N] = A[M,256] @ W[256,N] + bias[N]
// Block 128x128, BK=32, 8 warps (4x2), warp tile 32x64, mma.m16n8k16.
// W read from pre-transposed fp16 g_wt rows (2 LDG.128 per thread per iter).
// Double-buffered swizzled smem, ldmatrix fragment loads, reg prefetch.
// ---------------------------------------------------------------------------
template<bool GATHER, bool AHALF, bool CHALF>
__global__ __launch_bounds__(256, 2) void gemm_f16_kernel(
    const void* __restrict__ Av, const __half* __restrict__ Wt,
    const float* __restrict__ bias, void* __restrict__ Cv, int N)
{
    __shared__ __half Asm[2][128 * 32];
    __shared__ __half Wsm[2][128 * 32];

    const int t    = threadIdx.x;
    const int bm   = blockIdx.y, bn = blockIdx.x;
    const int lane = t & 31, warp = t >> 5;
    const int wm   = warp >> 1;
    const int wnn  = warp & 1;
    const int g    = lane >> 2;
    const int tq   = lane & 3;
    const int l15  = lane & 15, lhi = lane >> 4;

    // A stager: thread -> (row t>>1, k16-block t&1)
    const int arow = t >> 1, as_ = t & 1;
    size_t aoff;
    if (GATHER) {
        const int r    = bm * 128 + arow;
        const int wwin = r >> 6, p = r & 63;
        const int b    = wwin >> 8, widx = wwin & 255;
        const int wy   = widx >> 4, wx = widx & 15;
        const int py   = wy * 8 + (p >> 3);
        const int px   = wx * 8 + (p & 7);
        aoff = (((size_t)b * IMGH + py) * IMGW + px) * DIM;
    } else {
        aoff = (size_t)(bm * 128 + arow) * DIM;
    }
    const float*  ArowF = (const float*)Av + aoff;
    const __half* ArowH = (const __half*)Av + aoff;
    const uint32_t aSt0 = sw_off(arow, 2 * as_);
    const uint32_t aSt1 = sw_off(arow, 2 * as_ + 1);

    // W stager: thread -> (n-row t>>1, k16-block t&1); 16 halves contiguous
    const int wn_ = t >> 1, kbw = t & 1;
    const __half* Wrow = Wt + (size_t)(bn * 128 + wn_) * DIM + kbw * 16;
    const uint32_t wSt0 = sw_off(wn_, 2 * kbw);
    const uint32_t wSt1 = sw_off(wn_, 2 * kbw + 1);

    const uint32_t aBase = (uint32_t)__cvta_generic_to_shared(Asm);
    const uint32_t wBase = (uint32_t)__cvta_generic_to_shared(Wsm);
    uint32_t aRow[2]; int aS[2];
    #pragma unroll
    for (int mi = 0; mi < 2; mi++) {
        int row = wm * 32 + mi * 16 + l15;
        aRow[mi] = aBase + row * 64;
        aS[mi]   = (row >> 1) & 3;
    }
    uint32_t bRow[4]; int bS[4];
    #pragma unroll
    for (int nt = 0; nt < 4; nt++) {
        int row = wnn * 64 + nt * 16 + l15;
        bRow[nt] = wBase + row * 64;
        bS[nt]   = (row >> 1) & 3;
    }

    float acc[2][8][4];
    #pragma unroll
    for (int mi = 0; mi < 2; mi++)
        #pragma unroll
        for (int ni = 0; ni < 8; ni++)
            #pragma unroll
            for (int j = 0; j < 4; j++) acc[mi][ni][j] = 0.f;

    uint32_t apk[8], wpk[8];

    // ---- prologue: load iter 0 and store to buffer 0 ----
    {
        if (AHALF) {
            const uint4* ap = (const uint4*)(ArowH + as_ * 16);
            uint4 u0 = ap[0], u1 = ap[1];
            apk[0]=u0.x; apk[1]=u0.y; apk[2]=u0.z; apk[3]=u0.w;
            apk[4]=u1.x; apk[5]=u1.y; apk[6]=u1.z; apk[7]=u1.w;
        } else {
            const float* ap = ArowF + as_ * 16;
            float4 v0 = *(const float4*)(ap);
            float4 v1 = *(const float4*)(ap + 4);
            float4 v2 = *(const float4*)(ap + 8);
            float4 v3 = *(const float4*)(ap + 12);
            apk[0]=pkh2(v0.x,v0.y); apk[1]=pkh2(v0.z,v0.w);
            apk[2]=pkh2(v1.x,v1.y); apk[3]=pkh2(v1.z,v1.w);
            apk[4]=pkh2(v2.x,v2.y); apk[5]=pkh2(v2.z,v2.w);
            apk[6]=pkh2(v3.x,v3.y); apk[7]=pkh2(v3.z,v3.w);
        }
        const uint4* wp4 = (const uint4*)Wrow;
        uint4 w0 = wp4[0], w1 = wp4[1];
        wpk[0]=w0.x; wpk[1]=w0.y; wpk[2]=w0.z; wpk[3]=w0.w;
        wpk[4]=w1.x; wpk[5]=w1.y; wpk[6]=w1.z; wpk[7]=w1.w;

        char* aT = (char*)Asm[0];
        char* wT = (char*)Wsm[0];
        *(uint4*)(aT + aSt0) = make_uint4(apk[0], apk[1], apk[2], apk[3]);
        *(uint4*)(aT + aSt1) = make_uint4(apk[4], apk[5], apk[6], apk[7]);
        *(uint4*)(wT + wSt0) = make_uint4(wpk[0], wpk[1], wpk[2], wpk[3]);
        *(uint4*)(wT + wSt1) = make_uint4(wpk[4], wpk[5], wpk[6], wpk[7]);
    }
    __syncthreads();

    for (int it = 0; it < 8; it++) {
        const uint32_t bufOff = (uint32_t)(it & 1) * 8192;

        // ---- issue next iteration's global loads ----
        if (it < 7) {
            const int k0 = (it + 1) * 32;
            if (AHALF) {
                const uint4* ap = (const uint4*)(ArowH + k0 + as_ * 16);
                uint4 u0 = ap[0], u1 = ap[1];
                apk[0]=u0.x; apk[1]=u0.y; apk[2]=u0.z; apk[3]=u0.w;
                apk[4]=u1.x; apk[5]=u1.y; apk[6]=u1.z; apk[7]=u1.w;
            } else {
                const float* ap = ArowF + k0 + as_ * 16;
                float4 v0 = *(const float4*)(ap);
                float4 v1 = *(const float4*)(ap + 4);
                float4 v2 = *(const float4*)(ap + 8);
                float4 v3 = *(const float4*)(ap + 12);
                apk[0]=pkh2(v0.x,v0.y); apk[1]=pkh2(v0.z,v0.w);
                apk[2]=pkh2(v1.x,v1.y); apk[3]=pkh2(v1.z,v1.w);
                apk[4]=pkh2(v2.x,v2.y); apk[5]=pkh2(v2.z,v2.w);
                apk[6]=pkh2(v3.x,v3.y); apk[7]=pkh2(v3.z,v3.w);
            }
            const uint4* wp4 = (const uint4*)(Wrow + k0);
            uint4 w0 = wp4[0], w1 = wp4[1];
            wpk[0]=w0.x; wpk[1]=w0.y; wpk[2]=w0.z; wpk[3]=w0.w;
            wpk[4]=w1.x; wpk[5]=w1.y; wpk[6]=w1.z; wpk[7]=w1.w;
        }

        // ---- compute 2 k16 blocks from current buffer ----
        #pragma unroll
        for (int kb = 0; kb < 2; kb++) {
            const int kc = 2 * kb + lhi;
            uint32_t a[2][4];
            #pragma unroll
            for (int mi = 0; mi < 2; mi++)
                ldsm_x4(a[mi][0], a[mi][1], a[mi][2], a[mi][3],
                        aRow[mi] + bufOff + (uint32_t)(((kc ^ aS[mi]) << 4)));
            uint32_t b[4][4];
            #pragma unroll
            for (int nt = 0; nt < 4; nt++)
                ldsm_x4(b[nt][0], b[nt][1], b[nt][2], b[nt][3],
                        bRow[nt] + bufOff + (uint32_t)(((kc ^ bS[nt]) << 4)));
            #pragma unroll
            for (int mi = 0; mi < 2; mi++)
                #pragma unroll
                for (int nt = 0; nt < 4; nt++) {
                    mma_f16(acc[mi][2*nt],   a[mi][0], a[mi][1], a[mi][2], a[mi][3],
                            b[nt][0], b[nt][2]);
                    mma_f16(acc[mi][2*nt+1], a[mi][0], a[mi][1], a[mi][2], a[mi][3],
                            b[nt][1], b[nt][3]);
                }
        }

        // ---- store next iteration into the other buffer ----
        if (it < 7) {
            char* aT = (char*)Asm[(it + 1) & 1];
            char* wT = (char*)Wsm[(it + 1) & 1];
            *(uint4*)(aT + aSt0) = make_uint4(apk[0], apk[1], apk[2], apk[3]);
            *(uint4*)(aT + aSt1) = make_uint4(apk[4], apk[5], apk[6], apk[7]);
            *(uint4*)(wT + wSt0) = make_uint4(wpk[0], wpk[1], wpk[2], wpk[3]);
            *(uint4*)(wT + wSt1) = make_uint4(wpk[4], wpk[5], wpk[6], wpk[7]);
        }
        __syncthreads();
    }

    // ---- epilogue ----
    #pragma unroll
    for (int mi = 0; mi < 2; mi++) {
        const int r0 = bm * 128 + wm * 32 + mi * 16 + g;
        #pragma unroll
        for (int ni = 0; ni < 8; ni++) {
            const int col = bn * 128 + wnn * 64 + ni * 8 + 2 * tq;
            float2 bv = *(const float2*)(bias + col);
            float c0 = acc[mi][ni][0] + bv.x, c1 = acc[mi][ni][1] + bv.y;
            float c2 = acc[mi][ni][2] + bv.x, c3 = acc[mi][ni][3] + bv.y;
            if (CHALF) {
                __half* C = (__half*)Cv;
                *(uint32_t*)(C + (size_t)r0 * N + col)       = pkh2(c0, c1);
                *(uint32_t*)(C + (size_t)(r0 + 8) * N + col) = pkh2(c2, c3);
            } else {
                float* C = (float*)Cv;
                *(float2*)(C + (size_t)r0 * N + col)       = make_float2(c0, c1);
                *(float2*)(C + (size_t)(r0 + 8) * N + col) = make_float2(c2, c3);
            }
        }
    }
}

// ---------------------------------------------------------------------------
// fp16 tensor-core attention, register-resident P (unchanged from R12).
// ---------------------------------------------------------------------------
__global__ __launch_bounds__(256) void attn_mma_kernel()
{
    __shared__ uint2  Qs2[256][12];
    __shared__ uint2  Kt2[64][12];
    __shared__ __half Vt_h[32][72];
    __shared__ __half Bs_h[64][66];

    const int blk = blockIdx.x;
    const int win = blk >> 3;
    const int h   = blk & 7;
    const int t   = threadIdx.x;
    const int lane = t & 31, warp = t >> 5;
    const int g   = lane >> 2;
    const int tq  = lane & 3;
    const int slot = (tq + ((g & 3) + 2 * (g >> 2))) & 3;

    {
        const __half* qp = g_q + ((size_t)(win * NQ + t)) * DIM + h * HD;
        const int rot = ((t & 3) + 2 * ((t >> 2) & 1)) & 3;
        const uint4* qp4 = (const uint4*)qp;
        uint4 u0 = qp4[0], u1 = qp4[1], u2 = qp4[2], u3 = qp4[3];
        uint32_t w[16] = {u0.x,u0.y,u0.z,u0.w, u1.x,u1.y,u1.z,u1.w,
                          u2.x,u2.y,u2.z,u2.w, u3.x,u3.y,u3.z,u3.w};
        #pragma unroll
        for (int q = 0; q < 4; q++) {
            Qs2[t][((q + rot) & 3)]     = make_uint2(w[q],     w[q + 4]);
            Qs2[t][4 + ((q + rot) & 3)] = make_uint2(w[8 + q], w[12 + q]);
        }
    }
    if (t < 64) {
        const __half* kp = g_kv + (size_t)(win * WS2 + t) * 512 + h * HD;
        const int rot = ((t & 3) + 2 * ((t >> 2) & 1)) & 3;
        const uint4* kp4 = (const uint4*)kp;
        uint4 u0 = kp4[0], u1 = kp4[1], u2 = kp4[2], u3 = kp4[3];
        uint32_t w[16] = {u0.x,u0.y,u0.z,u0.w, u1.x,u1.y,u1.z,u1.w,
                          u2.x,u2.y,u2.z,u2.w, u3.x,u3.y,u3.z,u3.w};
        #pragma unroll
        for (int q = 0; q < 4; q++) {
            Kt2[t][((q + rot) & 3)]     = make_uint2(w[q],     w[q + 4]);
            Kt2[t][4 + ((q + rot) & 3)] = make_uint2(w[8 + q], w[12 + q]);
        }
    } else if (t < 128) {
        const int key = t - 64;
        const __half2* vp2 = (const __half2*)(g_kv + (size_t)(win * WS2 + key) * 512
                                              + DIM + h * HD);
        #pragma unroll
        for (int j = 0; j < 16; j++) {
            __half2 v = vp2[j];
            Vt_h[2 * j][key]     = __low2half(v);
            Vt_h[2 * j + 1][key] = __high2half(v);
        }
    }
    {
        const __half* gb = g_bias + h * 4096;
        #pragma unroll
        for (int i = 0; i < 2; i++) {
            int idx = t + i * 256;
            int qp = idx >> 3, c8 = (idx & 7) * 8;
            uint4 u = *(const uint4*)(gb + qp * 64 + c8);
            uint32_t* dst = (uint32_t*)((char*)&Bs_h[qp][0] + c8 * 2);
            dst[0] = u.x; dst[1] = u.y; dst[2] = u.z; dst[3] = u.w;
        }
    }
    __syncthreads();

    float acc[2][8][4];
    #pragma unroll
    for (int mi = 0; mi < 2; mi++)
        #pragma unroll
        for (int ni = 0; ni < 8; ni++)
            #pragma unroll
            for (int j = 0; j < 4; j++) acc[mi][ni][j] = 0.f;

    #pragma unroll
    for (int kb = 0; kb < 2; kb++) {
        const int c = kb * 4 + slot;
        uint2 lo[2], hi[2];
        #pragma unroll
        for (int mi = 0; mi < 2; mi++) {
            const int r0 = warp * 32 + mi * 16 + g;
            lo[mi] = Qs2[r0][c];
            hi[mi] = Qs2[r0 + 8][c];
        }
        uint2 bf[8];
        #pragma unroll
        for (int ni = 0; ni < 8; ni++)
            bf[ni] = Kt2[ni * 8 + g][c];
        #pragma unroll
        for (int mi = 0; mi < 2; mi++)
            #pragma unroll
            for (int ni = 0; ni < 8; ni++)
                mma_f16(acc[mi][ni], lo[mi].x, hi[mi].x, lo[mi].y, hi[mi].y,
                        bf[ni].x, bf[ni].y);
    }

    const float scale = 0.17677669529663687f;
    float inv_[2][2];
    #pragma unroll
    for (int mi = 0; mi < 2; mi++) {
        const int rA = warp * 32 + mi * 16 + g;
        const int qA = rA & 63, qB = (rA + 8) & 63;
        float mA = -1e30f, mB = -1e30f;
        #pragma unroll
        for (int ni = 0; ni < 8; ni++) {
            const int col = ni * 8 + 2 * tq;
            float2 bA = __half22float2(*(const __half2*)&Bs_h[qA][col]);
            float2 bB = __half22float2(*(const __half2*)&Bs_h[qB][col]);
            acc[mi][ni][0] = acc[mi][ni][0] * scale + bA.x;
            acc[mi][ni][1] = acc[mi][ni][1] * scale + bA.y;
            acc[mi][ni][2] = acc[mi][ni][2] * scale + bB.x;
            acc[mi][ni][3] = acc[mi][ni][3] * scale + bB.y;
            mA = fmaxf(mA, fmaxf(acc[mi][ni][0], acc[mi][ni][1]));
            mB = fmaxf(mB, fmaxf(acc[mi][ni][2], acc[mi][ni][3]));
        }
        mA = fmaxf(mA, __shfl_xor_sync(0xffffffff, mA, 1));
        mA = fmaxf(mA, __shfl_xor_sync(0xffffffff, mA, 2));
        mB = fmaxf(mB, __shfl_xor_sync(0xffffffff, mB, 1));
        mB = fmaxf(mB, __shfl_xor_sync(0xffffffff, mB, 2));
        float sA = 0.f, sB = 0.f;
        #pragma unroll
        for (int ni = 0; ni < 8; ni++) {
            float e0 = __expf(acc[mi][ni][0] - mA);
            float e1 = __expf(acc[mi][ni][1] - mA);
            float e2 = __expf(acc[mi][ni][2] - mB);
            float e3 = __expf(acc[mi][ni][3] - mB);
            acc[mi][ni][0] = e0; acc[mi][ni][1] = e1;
            acc[mi][ni][2] = e2; acc[mi][ni][3] = e3;
            sA += e0 + e1; sB += e2 + e3;
        }
        sA += __shfl_xor_sync(0xffffffff, sA, 1);
        sA += __shfl_xor_sync(0xffffffff, sA, 2);
        sB += __shfl_xor_sync(0xffffffff, sB, 1);
        sB += __shfl_xor_sync(0xffffffff, sB, 2);
        inv_[mi][0] = 1.f / sA;
        inv_[mi][1] = 1.f / sB;
    }

    float o[2][4][4];
    #pragma unroll
    for (int mi = 0; mi < 2; mi++)
        #pragma unroll
        for (int ni = 0; ni < 4; ni++)
            #pragma unroll
            for (int j = 0; j < 4; j++) o[mi][ni][j] = 0.f;

    #pragma unroll
    for (int kb = 0; kb < 4; kb++) {
        uint32_t a0[2], a1[2], a2[2], a3[2];
        #pragma unroll
        for (int mi = 0; mi < 2; mi++) {
            a0[mi] = pkh2(acc[mi][2*kb][0],     acc[mi][2*kb][1]);
            a1[mi] = pkh2(acc[mi][2*kb][2],     acc[mi][2*kb][3]);
            a2[mi] = pkh2(acc[mi][2*kb+1][0],   acc[mi][2*kb+1][1]);
            a3[mi] = pkh2(acc[mi][2*kb+1][2],   acc[mi][2*kb+1][3]);
        }
        #pragma unroll
        for (int ni = 0; ni < 4; ni++) {
            const __half* vrow = &Vt_h[ni * 8 + g][0];
            uint32_t b0 = *(const uint32_t*)(vrow + 16 * kb + 2 * tq);
            uint32_t b1 = *(const uint32_t*)(vrow + 16 * kb + 8 + 2 * tq);
            #pragma unroll
            for (int mi = 0; mi < 2; mi++)
                mma_f16(o[mi][ni], a0[mi], a1[mi], a2[mi], a3[mi], b0, b1);
        }
    }

    #pragma unroll
    for (int mi = 0; mi < 2; mi++) {
        const int r = win * NQ + warp * 32 + mi * 16 + g;
        const float ivA = inv_[mi][0], ivB = inv_[mi][1];
        #pragma unroll
        for (int ni = 0; ni < 4; ni++) {
            const int col = h * HD + ni * 8 + 2 * tq;
            *(uint32_t*)(g_att + (size_t)r * DIM + col) =
                pkh2(o[mi][ni][0] * ivA, o[mi][ni][1] * ivA);
            *(uint32_t*)(g_att + (size_t)(r + 8) * DIM + col) =
                pkh2(o[mi][ni][2] * ivB, o[mi][ni][3] * ivB);
        }
    }
}

// ---------------------------------------------------------------------------
extern "C" void kernel_launch(void* const* d_in, const int* in_sizes, int n_in,
                              void* d_out, int out_size)
{
    const float* gauss = (const float*)d_in[0];
    const float* img   = (const float*)d_in[1];
    const float* btab  = (const float*)d_in[2];
    const float* Wq    = (const float*)d_in[3];
    const float* bq    = (const float*)d_in[4];
    const float* Wkv   = (const float*)d_in[5];
    const float* bkv   = (const float*)d_in[6];
    const float* Wp    = (const float*)d_in[7];
    const float* bp    = (const float*)d_in[8];
    float* out = (float*)d_out;

    void* pq = nullptr;   cudaGetSymbolAddress(&pq, g_q);
    void* pkv = nullptr;  cudaGetSymbolAddress(&pkv, g_kv);
    void* pa = nullptr;   cudaGetSymbolAddress(&pa, g_att);
    void* pwt = nullptr;  cudaGetSymbolAddress(&pwt, g_wt);
    const __half* wt = (const __half*)pwt;

    // 0) prep: bias table + transposed fp16 weights
    bias_prep_kernel<<<HEADS, 256>>>(btab);
    w_prep_kernel<<<1024, 256>>>(Wq, Wkv, Wp);
    // 1) Q projection: fp32 A -> fp16 C
    gemm_f16_kernel<false, false, true>
        <<<dim3(DIM / 128, ROWS_Q / 128), 256>>>(gauss, wt, bq, pq, DIM);
    // 2) KV projection (window gather): fp32 A -> fp16 C
    gemm_f16_kernel<true, false, true>
        <<<dim3((2 * DIM) / 128, ROWS_KV / 128), 256>>>(img, wt + 256 * DIM, bkv, pkv, 2 * DIM);
    // 3) Attention (fp16 MMA, register-resident P, precomputed bias)
    attn_mma_kernel<<<BW * HEADS, 256>>>();
    // 4) Output projection: fp16 A -> fp32 C (d_out)
    gemm_f16_kernel<false, true, false>
        <<<dim3(DIM / 128, ROWS_Q / 128), 256>>>(pa, wt + 768 * DIM, bp, out, DIM);
}